// round 14
// baseline (speedup 1.0000x reference)
#include <cuda_runtime.h>
#include <cuda_bf16.h>
#include <cstdint>

// Problem constants
#define Bsz 64
#define Nn  577
#define Dd  768
#define Hh  12
#define DH  64
#define DFF 3072
#define Mrows (Bsz*Nn)          // 36928
#define NUM_PATCHES 576
#define N_ALPHA 288
#define MC_SAMPLES 16
#define VSTR 640                // padded token stride for row0
#define PSTR 136                // bf16 P row stride (smem)

// ---------------- scratch (static device globals; no allocation) ------------
__device__ float g_x1 [(size_t)Mrows*Dd];
__device__ float g_x2 [(size_t)Mrows*Dd];
__device__ __nv_bfloat16 g_ah [(size_t)Mrows*Dd];      // LN1 out hi
__device__ __nv_bfloat16 g_al [(size_t)Mrows*Dd];      // LN1 out lo
__device__ __nv_bfloat16 g_qkvh[(size_t)Mrows*3*Dd];   // qkv result (bf16)
__device__ float g_row0[(size_t)Bsz*Hh*VSTR];          // raw cls scores per bh
__device__ float g_q0ex[(size_t)Bsz*Dd];               // exact fp32 q row 0 per batch
__device__ float g_wt  [(size_t)Bsz*Hh*Dd];            // w~ = Wk q0 per (b,h)
__device__ float g_c0  [Bsz*Hh];                       // q0 . bk per (b,h)
__device__ __nv_bfloat16 g_ob [(size_t)Mrows*Dd];      // attention out (bf16)
__device__ __nv_bfloat16 g_hb [(size_t)Mrows*Dd];      // LN2 out (bf16)
__device__ __nv_bfloat16 g_ffb[(size_t)Mrows*DFF];     // gelu(fc1) out (bf16)
__device__ __nv_bfloat16 g_wqkvT[(size_t)(3*Dd)*Dd];
__device__ __nv_bfloat16 g_wprojT[(size_t)Dd*Dd];
__device__ __nv_bfloat16 g_wfc1T [(size_t)DFF*Dd];
__device__ __nv_bfloat16 g_wfc2T [(size_t)Dd*DFF];
__device__ int   g_selidx[Bsz*N_ALPHA];

// ---------------- LayerNorm (bf16 out) and split hi/lo variant ---------------
__global__ __launch_bounds__(256) void ln_kernel_bf16(
    const float* __restrict__ x, const float* __restrict__ g,
    const float* __restrict__ be, __nv_bfloat16* __restrict__ out)
{
    int row  = blockIdx.x*8 + (threadIdx.x>>5);
    int lane = threadIdx.x & 31;
    if (row >= Mrows) return;
    const float4* xr = (const float4*)(x + (size_t)row*Dd);
    float4 v[6];
    float s = 0.f, sq = 0.f;
    #pragma unroll
    for (int i = 0; i < 6; i++) {
        v[i] = xr[lane + 32*i];
        s  += v[i].x + v[i].y + v[i].z + v[i].w;
        sq += v[i].x*v[i].x + v[i].y*v[i].y + v[i].z*v[i].z + v[i].w*v[i].w;
    }
    #pragma unroll
    for (int off = 16; off; off >>= 1) {
        s  += __shfl_xor_sync(0xffffffff, s,  off);
        sq += __shfl_xor_sync(0xffffffff, sq, off);
    }
    float mu  = s * (1.0f/Dd);
    float var = sq * (1.0f/Dd) - mu*mu;
    float rinv = rsqrtf(var + 1e-6f);
    const float4* gp = (const float4*)g;
    const float4* bp = (const float4*)be;
    __nv_bfloat162* op = (__nv_bfloat162*)(out + (size_t)row*Dd);
    #pragma unroll
    for (int i = 0; i < 6; i++) {
        int c = lane + 32*i;
        float4 gg = gp[c], bb = bp[c], vv = v[i];
        float r0 = (vv.x-mu)*rinv*gg.x + bb.x;
        float r1 = (vv.y-mu)*rinv*gg.y + bb.y;
        float r2 = (vv.z-mu)*rinv*gg.z + bb.z;
        float r3 = (vv.w-mu)*rinv*gg.w + bb.w;
        op[c*2+0] = __floats2bfloat162_rn(r0, r1);
        op[c*2+1] = __floats2bfloat162_rn(r2, r3);
    }
}

__global__ __launch_bounds__(256) void ln_split_kernel(
    const float* __restrict__ x, const float* __restrict__ g,
    const float* __restrict__ be,
    __nv_bfloat16* __restrict__ oh, __nv_bfloat16* __restrict__ ol)
{
    int row  = blockIdx.x*8 + (threadIdx.x>>5);
    int lane = threadIdx.x & 31;
    if (row >= Mrows) return;
    const float4* xr = (const float4*)(x + (size_t)row*Dd);
    float4 v[6];
    float s = 0.f, sq = 0.f;
    #pragma unroll
    for (int i = 0; i < 6; i++) {
        v[i] = xr[lane + 32*i];
        s  += v[i].x + v[i].y + v[i].z + v[i].w;
        sq += v[i].x*v[i].x + v[i].y*v[i].y + v[i].z*v[i].z + v[i].w*v[i].w;
    }
    #pragma unroll
    for (int off = 16; off; off >>= 1) {
        s  += __shfl_xor_sync(0xffffffff, s,  off);
        sq += __shfl_xor_sync(0xffffffff, sq, off);
    }
    float mu  = s * (1.0f/Dd);
    float var = sq * (1.0f/Dd) - mu*mu;
    float rinv = rsqrtf(var + 1e-6f);
    const float4* gp = (const float4*)g;
    const float4* bp = (const float4*)be;
    __nv_bfloat162* oph = (__nv_bfloat162*)(oh + (size_t)row*Dd);
    __nv_bfloat162* opl = (__nv_bfloat162*)(ol + (size_t)row*Dd);
    #pragma unroll
    for (int i = 0; i < 6; i++) {
        int c = lane + 32*i;
        float4 gg = gp[c], bb = bp[c], vv = v[i];
        float r[4];
        r[0] = (vv.x-mu)*rinv*gg.x + bb.x;
        r[1] = (vv.y-mu)*rinv*gg.y + bb.y;
        r[2] = (vv.z-mu)*rinv*gg.z + bb.z;
        r[3] = (vv.w-mu)*rinv*gg.w + bb.w;
        __nv_bfloat16 h0 = __float2bfloat16(r[0]);
        __nv_bfloat16 h1 = __float2bfloat16(r[1]);
        __nv_bfloat16 h2 = __float2bfloat16(r[2]);
        __nv_bfloat16 h3 = __float2bfloat16(r[3]);
        oph[c*2+0] = __nv_bfloat162(h0, h1);
        oph[c*2+1] = __nv_bfloat162(h2, h3);
        opl[c*2+0] = __floats2bfloat162_rn(r[0]-__bfloat162float(h0), r[1]-__bfloat162float(h1));
        opl[c*2+1] = __floats2bfloat162_rn(r[2]-__bfloat162float(h2), r[3]-__bfloat162float(h3));
    }
}

// ---------------- weight transpose: W[K][N] f32 -> Wt[N][K] bf16 -------------
__global__ void transpose_bf16_kernel(const float* __restrict__ W,
                                      __nv_bfloat16* __restrict__ Wt, int K, int N)
{
    __shared__ float tile[32][33];
    int k0 = blockIdx.y*32, n0 = blockIdx.x*32;
    int tx = threadIdx.x, ty = threadIdx.y;    // 32 x 8
    #pragma unroll
    for (int i = 0; i < 32; i += 8)
        tile[ty+i][tx] = W[(size_t)(k0+ty+i)*N + n0+tx];
    __syncthreads();
    #pragma unroll
    for (int i = 0; i < 32; i += 8)
        Wt[(size_t)(n0+ty+i)*K + k0+tx] = __float2bfloat16(tile[tx][ty+i]);
}

// ---------------- mma/ldmatrix helpers ----------------------------------------
__device__ __forceinline__ void mma16816(float* c, const uint32_t* a, const uint32_t* b) {
    asm volatile(
        "mma.sync.aligned.m16n8k16.row.col.f32.bf16.bf16.f32 "
        "{%0,%1,%2,%3}, {%4,%5,%6,%7}, {%8,%9}, {%0,%1,%2,%3};"
        : "+f"(c[0]), "+f"(c[1]), "+f"(c[2]), "+f"(c[3])
        : "r"(a[0]), "r"(a[1]), "r"(a[2]), "r"(a[3]), "r"(b[0]), "r"(b[1]));
}
__device__ __forceinline__ void ldsm4(uint32_t& r0, uint32_t& r1, uint32_t& r2, uint32_t& r3,
                                      uint32_t addr) {
    asm volatile("ldmatrix.sync.aligned.m8n8.x4.shared.b16 {%0,%1,%2,%3}, [%4];"
        : "=r"(r0), "=r"(r1), "=r"(r2), "=r"(r3) : "r"(addr));
}
__device__ __forceinline__ void ldsm4t(uint32_t& r0, uint32_t& r1, uint32_t& r2, uint32_t& r3,
                                       uint32_t addr) {
    asm volatile("ldmatrix.sync.aligned.m8n8.x4.trans.shared.b16 {%0,%1,%2,%3}, [%4];"
        : "=r"(r0), "=r"(r1), "=r"(r2), "=r"(r3) : "r"(addr));
}

// ---------------- tensor-core GEMM 128x128 (3-stage cp.async) ----------------
// MODE 1: Cf = res + ls[n]*(acc + bias)          (fp32 out)
// MODE 2: Cb = gelu_tanh(acc + bias)             (bf16 out)
// MODE 4: Cb = bf16(acc + bias)                  (bf16 out)
#define TILE_H 8192   // halves per 128x64 tile (16KB)

template<int MODE>
__global__ __launch_bounds__(256) void gemm_tc(
    const __nv_bfloat16* __restrict__ A,
    const __nv_bfloat16* __restrict__ Bt,
    const float* __restrict__ bias, const float* __restrict__ res,
    const float* __restrict__ ls,
    float* __restrict__ Cf, __nv_bfloat16* __restrict__ Cb,
    int M, int N, int K, int ldc)
{
    extern __shared__ __nv_bfloat16 smem[];
    const int SS = 2*TILE_H;

    int m0 = blockIdx.y*128, n0 = blockIdx.x*128;
    int t = threadIdx.x;
    int warp = t >> 5, lane = t & 31;
    int wm = warp & 1, wn = warp >> 1;
    int g = lane >> 2, tq = lane & 3;

    float acc[4][4][4] = {};
    int KT = K >> 6;

    const int OFF_A = 0;
    const int OFF_B = TILE_H;

    auto load_tile = [&](__nv_bfloat16* dst, const __nv_bfloat16* src,
                         int row0, int k0, int rows_tot, int ld) {
        #pragma unroll
        for (int i = 0; i < 4; i++) {
            int chunk = t + i*256;
            int row = chunk >> 3;
            int kc  = chunk & 7;
            uint32_t sa = (uint32_t)__cvta_generic_to_shared(
                dst + row*64 + ((kc*8) ^ ((row&7)*8)));
            const __nv_bfloat16* gp = src + (size_t)(row0+row)*ld + k0 + kc*8;
            int sz = (row0+row < rows_tot) ? 16 : 0;
            asm volatile("cp.async.cg.shared.global [%0], [%1], 16, %2;\n"
                         :: "r"(sa), "l"(gp), "r"(sz));
        }
    };
    auto load_stage = [&](int buf, int kt) {
        int k0 = kt*64;
        __nv_bfloat16* st = smem + buf*SS;
        load_tile(st + OFF_A, A,  m0, k0, M, K);
        load_tile(st + OFF_B, Bt, n0, k0, N, K);
        asm volatile("cp.async.commit_group;\n");
    };

    int arow[4], abase[4], asw[4];
    #pragma unroll
    for (int mt = 0; mt < 4; mt++) {
        arow[mt]  = wm*64 + mt*16 + (lane & 15);
        abase[mt] = arow[mt]*128;
        asw[mt]   = (arow[mt] & 7) * 16;
    }
    int ahi = ((lane >> 4) & 1) * 16;
    int brow[2], bbase[2], bsw[2];
    #pragma unroll
    for (int np = 0; np < 2; np++) {
        brow[np]  = wn*32 + np*16 + ((lane >> 4) << 3) + (lane & 7);
        bbase[np] = brow[np]*128;
        bsw[np]   = (brow[np] & 7) * 16;
    }
    int bhi = ((lane >> 3) & 1) * 16;

    load_stage(0, 0);
    if (KT > 1) load_stage(1, 1);

    for (int kt = 0; kt < KT; kt++) {
        int buf = kt % 3;
        if (kt + 1 < KT) {
            asm volatile("cp.async.wait_group 1;\n");
        } else {
            asm volatile("cp.async.wait_group 0;\n");
        }
        __syncthreads();
        if (kt + 2 < KT) load_stage((kt + 2) % 3, kt + 2);

        uint32_t baseA = (uint32_t)__cvta_generic_to_shared(smem + buf*SS + OFF_A);
        uint32_t baseB = (uint32_t)__cvta_generic_to_shared(smem + buf*SS + OFF_B);

        #pragma unroll
        for (int ks = 0; ks < 4; ks++) {
            uint32_t ah[4][4], bh[2][4];
            #pragma unroll
            for (int mt = 0; mt < 4; mt++) {
                int off = abase[mt] + ((ks*32 + ahi) ^ asw[mt]);
                ldsm4(ah[mt][0], ah[mt][1], ah[mt][2], ah[mt][3], baseA + off);
            }
            #pragma unroll
            for (int np = 0; np < 2; np++) {
                int off = bbase[np] + ((ks*32 + bhi) ^ bsw[np]);
                ldsm4(bh[np][0], bh[np][1], bh[np][2], bh[np][3], baseB + off);
            }
            #pragma unroll
            for (int mt = 0; mt < 4; mt++)
                #pragma unroll
                for (int ni = 0; ni < 4; ni++)
                    mma16816(acc[mt][ni], ah[mt], &bh[ni>>1][(ni&1)*2]);
        }
    }

    #pragma unroll
    for (int mi = 0; mi < 4; mi++) {
        #pragma unroll
        for (int hh = 0; hh < 2; hh++) {
            int m = m0 + wm*64 + mi*16 + g + hh*8;
            if (m >= M) continue;
            #pragma unroll
            for (int ni = 0; ni < 4; ni++) {
                int n = n0 + wn*32 + ni*8 + tq*2;
                float v0 = acc[mi][ni][hh*2+0] + bias[n];
                float v1 = acc[mi][ni][hh*2+1] + bias[n+1];
                size_t o = (size_t)m*ldc + n;
                if (MODE == 1) {
                    Cf[o]   = res[o]   + ls[n]  *v0;
                    Cf[o+1] = res[o+1] + ls[n+1]*v1;
                } else if (MODE == 2) {
                    float c0 = 0.7978845608028654f*(v0 + 0.044715f*v0*v0*v0);
                    float c1 = 0.7978845608028654f*(v1 + 0.044715f*v1*v1*v1);
                    v0 = 0.5f*v0*(1.0f + tanhf(c0));
                    v1 = 0.5f*v1*(1.0f + tanhf(c1));
                    *(__nv_bfloat162*)(Cb + o) = __floats2bfloat162_rn(v0, v1);
                } else {
                    *(__nv_bfloat162*)(Cb + o) = __floats2bfloat162_rn(v0, v1);
                }
            }
        }
    }
}

// ---------------- exact fp32 q row-0 per batch: LN1(x[b,0]) @ Wq + bq ---------
__global__ __launch_bounds__(768) void q0exact_kernel(
    const float* __restrict__ x, const float* __restrict__ g,
    const float* __restrict__ be, const float* __restrict__ w_qkv,
    const float* __restrict__ b_qkv, float* __restrict__ q0ex)
{
    __shared__ float ln0[Dd];
    __shared__ float rs[24], rq[24];
    int b = blockIdx.x, t = threadIdx.x;
    int lane = t & 31, w = t >> 5;
    float v = x[(size_t)b*Nn*Dd + t];          // token 0
    float s = v, sq = v*v;
    #pragma unroll
    for (int off = 16; off; off >>= 1) {
        s  += __shfl_xor_sync(0xffffffff, s,  off);
        sq += __shfl_xor_sync(0xffffffff, sq, off);
    }
    if (lane == 0) { rs[w] = s; rq[w] = sq; }
    __syncthreads();
    if (t < 32) {
        float a = (t < 24) ? rs[t] : 0.f;
        float bb = (t < 24) ? rq[t] : 0.f;
        #pragma unroll
        for (int off = 16; off; off >>= 1) {
            a  += __shfl_xor_sync(0xffffffff, a,  off);
            bb += __shfl_xor_sync(0xffffffff, bb, off);
        }
        if (t == 0) { rs[0] = a; rq[0] = bb; }
    }
    __syncthreads();
    float mu = rs[0] * (1.0f/Dd);
    float var = rq[0] * (1.0f/Dd) - mu*mu;
    float rinv = rsqrtf(var + 1e-6f);
    ln0[t] = (v-mu)*rinv*g[t] + be[t];
    __syncthreads();
    float acc = b_qkv[t];                      // Q region col t
    #pragma unroll 8
    for (int k = 0; k < Dd; k++)
        acc += ln0[k] * w_qkv[(size_t)k*(3*Dd) + t];
    q0ex[(size_t)b*Dd + t] = acc;
}

// ---------------- w~ = Wk q0 per (b,h); c0 = q0 . bk --------------------------
__global__ __launch_bounds__(256) void wtilde_kernel(
    const float* __restrict__ w_qkv, const float* __restrict__ b_qkv,
    const float* __restrict__ q0ex, float* __restrict__ wt, float* __restrict__ c0g)
{
    __shared__ float q0s[64];
    int bh = blockIdx.x;
    int b = bh / Hh, h = bh - b*Hh;
    int t = threadIdx.x;
    if (t < 64) q0s[t] = q0ex[(size_t)b*Dd + h*DH + t];
    __syncthreads();
    #pragma unroll
    for (int i = 0; i < 3; i++) {
        int k = t + 256*i;
        const float* wr = w_qkv + (size_t)k*(3*Dd) + Dd + h*DH;
        float acc = 0.f;
        #pragma unroll
        for (int d = 0; d < 64; d++) acc += wr[d] * q0s[d];
        wt[(size_t)bh*Dd + k] = acc;
    }
    if (t == 0) {
        float c = 0.f;
        #pragma unroll
        for (int d = 0; d < 64; d++) c += q0s[d] * b_qkv[Dd + h*DH + d];
        c0g[bh] = c;
    }
}

// ---------------- row0: per (token-chunk, b) block, all heads in smem ---------
__global__ __launch_bounds__(512) void row0_kernel(
    const __nv_bfloat16* __restrict__ ah, const __nv_bfloat16* __restrict__ al,
    const float* __restrict__ wt, const float* __restrict__ c0g,
    float* __restrict__ row0g)
{
    __shared__ float ws[Hh*Dd];       // 36 KB
    __shared__ float c0s[Hh];
    int b = blockIdx.y, chunk = blockIdx.x;
    int t = threadIdx.x, lane = t & 31, w = t >> 5;   // 16 warps
    for (int i = t; i < Hh*Dd; i += 512)
        ws[i] = wt[(size_t)b*Hh*Dd + i];
    if (t < Hh) c0s[t] = c0g[b*Hh + t];
    __syncthreads();

    #pragma unroll
    for (int it = 0; it < 8; it++) {
        int tok = chunk*128 + it*16 + w;
        if (tok >= Nn) break;
        const __nv_bfloat162* ar = (const __nv_bfloat162*)(ah + ((size_t)(b*Nn + tok))*Dd);
        const __nv_bfloat162* lr = (const __nv_bfloat162*)(al + ((size_t)(b*Nn + tok))*Dd);
        float af[24];
        #pragma unroll
        for (int j = 0; j < 12; j++) {
            int k2 = lane + 32*j;
            __nv_bfloat162 a2 = ar[k2], l2 = lr[k2];
            af[2*j]   = __low2float(a2)  + __low2float(l2);
            af[2*j+1] = __high2float(a2) + __high2float(l2);
        }
        #pragma unroll
        for (int h = 0; h < Hh; h++) {
            const float* wsr = ws + h*Dd;
            float s = 0.f;
            #pragma unroll
            for (int j = 0; j < 12; j++) {
                int k2 = lane + 32*j;
                s += af[2*j]*wsr[2*k2] + af[2*j+1]*wsr[2*k2+1];
            }
            #pragma unroll
            for (int off = 16; off; off >>= 1) s += __shfl_xor_sync(0xffffffff, s, off);
            if (lane == 0)
                row0g[(size_t)(b*Hh + h)*VSTR + tok] = (s + c0s[h]) * 0.125f;
        }
    }
}

// ---------------- flash attention: 128q per CTA, 2 subtiles share K/V --------
__global__ __launch_bounds__(256) void fattn_kernel(
    const __nv_bfloat16* __restrict__ qkvh, __nv_bfloat16* __restrict__ ob)
{
    extern __shared__ __nv_bfloat16 sm[];
    __nv_bfloat16* Qh = sm;                  // 128*64
    __nv_bfloat16* Kh = Qh + 8192;           // 128*64
    __nv_bfloat16* Vh = Kh + 8192;           // 128*64 ([tok][d])
    __nv_bfloat16* Pm = Vh + 8192;           // 64*PSTR
    float* part = (float*)(Pm + 64*PSTR);    // [2][64] warp-partial row sums
    float* lsum = part + 128;                // [128] accumulated denominators

    int bh = blockIdx.y;
    int b = bh / Hh, h = bh - b*Hh;
    int q0 = blockIdx.x * 128;
    int t = threadIdx.x, lane = t & 31, warp = t >> 5;
    int wm = warp >> 1, wn = warp & 1;
    int g = lane >> 2, tq = lane & 3;

    const __nv_bfloat16* qsrc = qkvh + (size_t)b*Nn*(3*Dd) + h*DH;
    const __nv_bfloat16* ksrc = qsrc + Dd;
    const __nv_bfloat16* vsrc = qsrc + 2*Dd;

    auto ldt = [&](__nv_bfloat16* dst, const __nv_bfloat16* src,
                   int r0_, int rtot, int ld, int nrows) {
        int iters = nrows >> 5;
        for (int i = 0; i < iters; i++) {
            int chunk = t + i*256;
            int row = chunk >> 3;
            int kc  = chunk & 7;
            uint32_t sa = (uint32_t)__cvta_generic_to_shared(
                dst + row*64 + ((kc*8) ^ ((row&7)*8)));
            const __nv_bfloat16* gp = src + (size_t)(r0_+row)*ld + kc*8;
            int sz = (r0_+row < rtot) ? 16 : 0;
            asm volatile("cp.async.cg.shared.global [%0], [%1], 16, %2;\n"
                         :: "r"(sa), "l"(gp), "r"(sz));
        }
    };

    ldt(Qh, qsrc, q0, Nn, 3*Dd, 128);
    asm volatile("cp.async.commit_group;\n");

    if (t < 128) lsum[t] = 0.f;
    float acc_o[2][4][4] = {};

    int ahi   = ((lane >> 4) & 1) * 16;
    int bhi   = ((lane >> 3) & 1) * 16;
    int vrow_l = lane & 15;
    int vcol_l = ((lane >> 4) & 1) * 8;

    uint32_t baseQh = (uint32_t)__cvta_generic_to_shared(Qh);
    uint32_t baseKh = (uint32_t)__cvta_generic_to_shared(Kh);
    uint32_t baseVh = (uint32_t)__cvta_generic_to_shared(Vh);
    uint32_t basePm = (uint32_t)__cvta_generic_to_shared(Pm);

    const int NCHUNK = (Nn + 127) / 128;
    for (int c = 0; c < NCHUNK; c++) {
        int k0 = c*128;
        int limit = Nn - k0; if (limit > 128) limit = 128;

        __syncthreads();                          // prior PV readers of Kh/Vh/Pm done
        ldt(Kh, ksrc, k0, Nn, 3*Dd, 128);
        ldt(Vh, vsrc, k0, Nn, 3*Dd, 128);
        asm volatile("cp.async.commit_group;\n");
        asm volatile("cp.async.wait_group 0;\n");
        __syncthreads();

        #pragma unroll
        for (int qs = 0; qs < 2; qs++) {
            if (qs == 1) __syncthreads();         // qs0 PV read of Pm done

            // ---- S = Qh[qs] @ Kh^T ----
            int arowS = qs*64 + wm*16 + (lane & 15);
            int aswS  = (arowS & 7) * 16;
            float accs[8][4] = {};
            #pragma unroll
            for (int ks = 0; ks < 4; ks++) {
                uint32_t a4[4];
                int offA = arowS*128 + ((ks*32 + ahi) ^ aswS);
                ldsm4(a4[0], a4[1], a4[2], a4[3], baseQh + offA);
                uint32_t bh4[4][4];
                #pragma unroll
                for (int np = 0; np < 4; np++) {
                    int brow = wn*64 + np*16 + ((lane >> 4) << 3) + (lane & 7);
                    int offB = brow*128 + ((ks*32 + bhi) ^ ((brow&7)*16));
                    ldsm4(bh4[np][0], bh4[np][1], bh4[np][2], bh4[np][3], baseKh + offB);
                }
                #pragma unroll
                for (int nf = 0; nf < 8; nf++)
                    mma16816(accs[nf], a4, &bh4[nf>>1][(nf&1)*2]);
            }

            // ---- exp in registers -> P bf16 + per-row sums ----
            {
                int r0 = wm*16 + g, r1 = r0 + 8;
                float sum0 = 0.f, sum1 = 0.f;
                #pragma unroll
                for (int nf = 0; nf < 8; nf++) {
                    int cc = wn*64 + nf*8 + tq*2;
                    bool m0 = cc < limit, m1 = cc + 1 < limit;
                    float e0 = m0 ? __expf(accs[nf][0]*0.125f) : 0.f;
                    float e1 = m1 ? __expf(accs[nf][1]*0.125f) : 0.f;
                    float e2 = m0 ? __expf(accs[nf][2]*0.125f) : 0.f;
                    float e3 = m1 ? __expf(accs[nf][3]*0.125f) : 0.f;
                    *(__nv_bfloat162*)(Pm + r0*PSTR + cc) = __floats2bfloat162_rn(e0, e1);
                    *(__nv_bfloat162*)(Pm + r1*PSTR + cc) = __floats2bfloat162_rn(e2, e3);
                    sum0 += e0 + e1;
                    sum1 += e2 + e3;
                }
                sum0 += __shfl_xor_sync(0xffffffff, sum0, 1);
                sum0 += __shfl_xor_sync(0xffffffff, sum0, 2);
                sum1 += __shfl_xor_sync(0xffffffff, sum1, 1);
                sum1 += __shfl_xor_sync(0xffffffff, sum1, 2);
                if (tq == 0) { part[wn*64 + r0] = sum0; part[wn*64 + r1] = sum1; }
            }
            __syncthreads();
            if (t < 64) lsum[qs*64 + t] += part[t] + part[64 + t];

            // ---- O[qs] += P @ V (trans ldmatrix on [tok][d]) ----
            #pragma unroll
            for (int s = 0; s < 8; s++) {
                uint32_t a4[4];
                uint32_t offP = (uint32_t)((wm*16 + (lane & 15))*PSTR*2 + s*32 + ((lane>>4)&1)*16);
                ldsm4(a4[0], a4[1], a4[2], a4[3], basePm + offP);
                uint32_t bv[2][4];
                #pragma unroll
                for (int np = 0; np < 2; np++) {
                    int row = s*16 + vrow_l;
                    int col = wn*32 + np*16 + vcol_l;
                    int off = row*128 + ((col*2) ^ ((row&7)*16));
                    ldsm4t(bv[np][0], bv[np][1], bv[np][2], bv[np][3], baseVh + off);
                }
                #pragma unroll
                for (int nf = 0; nf < 4; nf++)
                    mma16816(acc_o[qs][nf], a4, &bv[nf>>1][(nf&1)*2]);
            }
        }
    }

    __syncthreads();
    #pragma unroll
    for (int qs = 0; qs < 2; qs++) {
        int or0 = wm*16 + g, or1 = or0 + 8;
        float li0 = 1.f / lsum[qs*64 + or0];
        float li1 = 1.f / lsum[qs*64 + or1];
        int tok0 = q0 + qs*64 + or0, tok1 = q0 + qs*64 + or1;
        #pragma unroll
        for (int nf = 0; nf < 4; nf++) {
            int d = wn*32 + nf*8 + tq*2;
            if (tok0 < Nn)
                *(__nv_bfloat162*)(ob + ((size_t)(b*Nn + tok0))*Dd + h*DH + d) =
                    __floats2bfloat162_rn(acc_o[qs][nf][0]*li0, acc_o[qs][nf][1]*li0);
            if (tok1 < Nn)
                *(__nv_bfloat162*)(ob + ((size_t)(b*Nn + tok1))*Dd + h*DH + d) =
                    __floats2bfloat162_rn(acc_o[qs][nf][2]*li1, acc_o[qs][nf][3]*li1);
        }
    }
}

// ---------------- threefry2x32 for jax.random.key(42) ------------------------
__device__ __forceinline__ void tf_round(unsigned& x0, unsigned& x1, int r) {
    x0 += x1;
    x1 = ((x1 << r) | (x1 >> (32 - r))) ^ x0;
}
__device__ __forceinline__ uint2 threefry_42(unsigned c0, unsigned c1) {
    const unsigned k0 = 0u, k1 = 42u, k2 = 0x1BD11BDAu ^ 42u;
    unsigned x0 = c0 + k0, x1 = c1 + k1;
    tf_round(x0,x1,13); tf_round(x0,x1,15); tf_round(x0,x1,26); tf_round(x0,x1,6);
    x0 += k1; x1 += k2 + 1u;
    tf_round(x0,x1,17); tf_round(x0,x1,29); tf_round(x0,x1,16); tf_round(x0,x1,24);
    x0 += k2; x1 += k0 + 2u;
    tf_round(x0,x1,13); tf_round(x0,x1,15); tf_round(x0,x1,26); tf_round(x0,x1,6);
    x0 += k0; x1 += k1 + 3u;
    tf_round(x0,x1,17); tf_round(x0,x1,29); tf_round(x0,x1,16); tf_round(x0,x1,24);
    x0 += k1; x1 += k2 + 4u;
    tf_round(x0,x1,13); tf_round(x0,x1,15); tf_round(x0,x1,26); tf_round(x0,x1,6);
    x0 += k2; x1 += k0 + 5u;
    return make_uint2(x0, x1);
}

// ---------------- fused scoring: cls softmax-mean -> gumbel MC -> top-k -------
__global__ __launch_bounds__(608) void score_kernel(
    const float* __restrict__ row0g, int* __restrict__ selidx, float* __restrict__ adc)
{
    __shared__ float red[19];
    __shared__ float bcast;
    __shared__ float logit_sm[NUM_PATCHES];
    __shared__ float s_sm[NUM_PATCHES];
    __shared__ int flags[NUM_PATCHES];
    int b = blockIdx.x, t = threadIdx.x;
    int lane = t & 31, w = t >> 5;

    // phase 1: cls attention row, softmax per head, mean over heads
    float acc = 0.f;
    for (int h = 0; h < Hh; h++) {
        float s = (t < Nn) ? row0g[((size_t)(b*Hh + h))*VSTR + t] : -1e30f;
        float m = s;
        #pragma unroll
        for (int off = 16; off; off >>= 1) m = fmaxf(m, __shfl_xor_sync(0xffffffff, m, off));
        if (lane == 0) red[w] = m;
        __syncthreads();
        if (t == 0) {
            float mm = red[0];
            for (int i = 1; i < 19; i++) mm = fmaxf(mm, red[i]);
            bcast = mm;
        }
        __syncthreads();
        float M = bcast;
        float e = (t < Nn) ? expf(s - M) : 0.f;
        float sv = e;
        #pragma unroll
        for (int off = 16; off; off >>= 1) sv += __shfl_xor_sync(0xffffffff, sv, off);
        if (lane == 0) red[w] = sv;
        __syncthreads();
        if (t == 0) {
            float ss = 0.f;
            for (int i = 0; i < 19; i++) ss += red[i];
            bcast = ss;
        }
        __syncthreads();
        acc += e / bcast;
        __syncthreads();
    }
    if (t >= 1 && t < Nn) logit_sm[t-1] = logf(acc*(1.0f/Hh) + 1e-8f);
    __syncthreads();

    // phase 2: gumbel MC softmax (patch p = t for t < 576)
    float lg = (t < NUM_PATCHES) ? logit_sm[t] : -1e30f;
    float sacc = 0.f;
    for (int s = 0; s < MC_SAMPLES; s++) {
        float tt = -1e30f;
        if (t < NUM_PATCHES) {
            unsigned i = (unsigned)((s*Bsz + b)*NUM_PATCHES + t);
            uint2 r = threefry_42(0u, i);
            unsigned bits = r.x ^ r.y;
            float f = __uint_as_float(0x3f800000u | (bits >> 9)) - 1.0f;
            const float mn = 1e-6f, mx = 1.0f - 1e-6f;
            float u = fmaxf(f*(mx - mn) + mn, mn);
            float g = -logf(-logf(u));
            tt = (lg + g) * 2.0f;
        }
        float m = tt;
        #pragma unroll
        for (int off = 16; off; off >>= 1) m = fmaxf(m, __shfl_xor_sync(0xffffffff, m, off));
        if (lane == 0) red[w] = m;
        __syncthreads();
        if (t == 0) {
            float mm = red[0];
            for (int i = 1; i < 19; i++) mm = fmaxf(mm, red[i]);
            bcast = mm;
        }
        __syncthreads();
        float e = (t < NUM_PATCHES) ? expf(tt - bcast) : 0.f;
        __syncthreads();
        float sv = e;
        #pragma unroll
        for (int off = 16; off; off >>= 1) sv += __shfl_xor_sync(0xffffffff, sv, off);
        if (lane == 0) red[w] = sv;
        __syncthreads();
        if (t == 0) {
            float ss = 0.f;
            for (int i = 0; i < 19; i++) ss += red[i];
            bcast = ss;
        }
        __syncthreads();
        sacc += e / bcast;
        __syncthreads();
    }
    if (t < NUM_PATCHES) s_sm[t] = sacc * (1.0f/MC_SAMPLES);
    __syncthreads();

    // phase 3: stable top-k(288) + outputs
    if (t < NUM_PATCHES) {
        float sp = s_sm[t];
        int rank = 0;
        for (int j = 0; j < NUM_PATCHES; j++) {
            float sj = s_sm[j];
            rank += (sj > sp) || (sj == sp && j < t);
        }
        flags[t] = (rank < N_ALPHA) ? 1 : 0;
    }
    __syncthreads();
    if (t < NUM_PATCHES && flags[t]) {
        int pos = 0;
        for (int j = 0; j < t; j++) pos += flags[j];
        selidx[b*N_ALPHA + pos] = t + 1;
        adc[(size_t)b*(N_ALPHA+1) + pos + 1] = s_sm[t];
    }
    if (t == 0) adc[(size_t)b*(N_ALPHA+1)] = 1.0f;
}

// ---------------- gather selected tokens --------------------------------------
__global__ void gather_kernel(const float* __restrict__ x2,
                              const int* __restrict__ selidx, float* __restrict__ out)
{
    int j = blockIdx.x;
    int b = blockIdx.y;
    int row = (j == 0) ? 0 : selidx[b*N_ALPHA + j - 1];
    const float4* src = (const float4*)(x2 + ((size_t)b*Nn + row)*Dd);
    float4* dst = (float4*)(out + ((size_t)b*(N_ALPHA+1) + j)*Dd);
    dst[threadIdx.x] = src[threadIdx.x];
}

// ---------------- launch -------------------------------------------------------
extern "C" void kernel_launch(void* const* d_in, const int* in_sizes, int n_in,
                              void* d_out, int out_size)
{
    const float* x      = (const float*)d_in[0];
    const float* g1     = (const float*)d_in[1];
    const float* b1     = (const float*)d_in[2];
    const float* w_qkv  = (const float*)d_in[3];
    const float* b_qkv  = (const float*)d_in[4];
    const float* w_proj = (const float*)d_in[5];
    const float* b_proj = (const float*)d_in[6];
    const float* ls1    = (const float*)d_in[7];
    const float* g2     = (const float*)d_in[8];
    const float* b2     = (const float*)d_in[9];
    const float* w_fc1  = (const float*)d_in[10];
    const float* b_fc1  = (const float*)d_in[11];
    const float* w_fc2  = (const float*)d_in[12];
    const float* b_fc2  = (const float*)d_in[13];
    const float* ls2    = (const float*)d_in[14];
    float* out = (float*)d_out;

    float *x1, *x2, *row0, *q0ex, *wt, *c0;
    __nv_bfloat16 *ah, *al, *qkvh, *ob, *hb, *ffb;
    __nv_bfloat16 *wqkvT, *wprojT, *wfc1T, *wfc2T;
    int* selidx;
    cudaGetSymbolAddress((void**)&x1,     g_x1);
    cudaGetSymbolAddress((void**)&x2,     g_x2);
    cudaGetSymbolAddress((void**)&ah,     g_ah);
    cudaGetSymbolAddress((void**)&al,     g_al);
    cudaGetSymbolAddress((void**)&qkvh,   g_qkvh);
    cudaGetSymbolAddress((void**)&row0,   g_row0);
    cudaGetSymbolAddress((void**)&q0ex,   g_q0ex);
    cudaGetSymbolAddress((void**)&wt,     g_wt);
    cudaGetSymbolAddress((void**)&c0,     g_c0);
    cudaGetSymbolAddress((void**)&ob,     g_ob);
    cudaGetSymbolAddress((void**)&hb,     g_hb);
    cudaGetSymbolAddress((void**)&ffb,    g_ffb);
    cudaGetSymbolAddress((void**)&wqkvT,  g_wqkvT);
    cudaGetSymbolAddress((void**)&wprojT, g_wprojT);
    cudaGetSymbolAddress((void**)&wfc1T,  g_wfc1T);
    cudaGetSymbolAddress((void**)&wfc2T,  g_wfc2T);
    cudaGetSymbolAddress((void**)&selidx, g_selidx);

    int mblk = (Mrows + 7) / 8;
    int mtiles = (Mrows + 127) / 128;           // 289

    const int SMEM_NS = 3*2*TILE_H*2;           // 96KB (3 stages)
    cudaFuncSetAttribute(gemm_tc<4>, cudaFuncAttributeMaxDynamicSharedMemorySize, SMEM_NS);
    cudaFuncSetAttribute(gemm_tc<1>, cudaFuncAttributeMaxDynamicSharedMemorySize, SMEM_NS);
    cudaFuncSetAttribute(gemm_tc<2>, cudaFuncAttributeMaxDynamicSharedMemorySize, SMEM_NS);

    const int ATTN_SMEM = (8192+8192+8192+64*PSTR)*2 + (128+128)*4;
    cudaFuncSetAttribute(fattn_kernel, cudaFuncAttributeMaxDynamicSharedMemorySize, ATTN_SMEM);

    // 0. weight transposes
    transpose_bf16_kernel<<<dim3(3*Dd/32, Dd/32), dim3(32,8)>>>(w_qkv, wqkvT, Dd, 3*Dd);
    transpose_bf16_kernel<<<dim3(Dd/32,  Dd/32),  dim3(32,8)>>>(w_proj, wprojT, Dd,  Dd);
    transpose_bf16_kernel<<<dim3(DFF/32, Dd/32),  dim3(32,8)>>>(w_fc1,  wfc1T,  Dd,  DFF);
    transpose_bf16_kernel<<<dim3(Dd/32,  DFF/32), dim3(32,8)>>>(w_fc2,  wfc2T,  DFF, Dd);
    // 0b. exact q0 + w~ (selection-critical path, fp32 end-to-end)
    q0exact_kernel<<<Bsz, 768>>>(x, g1, b1, w_qkv, b_qkv, q0ex);
    wtilde_kernel<<<Bsz*Hh, 256>>>(w_qkv, b_qkv, q0ex, wt, c0);

    // 1. LN1 (split hi/lo bf16)
    ln_split_kernel<<<mblk, 256>>>(x, g1, b1, ah, al);
    // 2. QKV GEMM (N = 2304)
    gemm_tc<4><<<dim3(3*Dd/128, mtiles), 256, SMEM_NS>>>(
        ah, wqkvT, b_qkv, nullptr, nullptr, nullptr, qkvh, Mrows, 3*Dd, Dd, 3*Dd);
    // 3. cls-row scores (all heads per block; one pass over ah/al)
    row0_kernel<<<dim3((Nn+127)/128, Bsz), 512>>>(ah, al, wt, c0, row0);
    // 4. flash attention (128q/CTA, shared K/V chunks)
    fattn_kernel<<<dim3((Nn+127)/128, Bsz*Hh), 256, ATTN_SMEM>>>(qkvh, ob);
    // 5. proj + residual
    gemm_tc<1><<<dim3(Dd/128, mtiles), 256, SMEM_NS>>>(
        ob, wprojT, b_proj, x, ls1, x1, nullptr, Mrows, Dd, Dd, Dd);
    // 6. LN2 (bf16 out)
    ln_kernel_bf16<<<mblk, 256>>>(x1, g2, b2, hb);
    // 7. fc1 + gelu
    gemm_tc<2><<<dim3(DFF/128, mtiles), 256, SMEM_NS>>>(
        hb, wfc1T, b_fc1, nullptr, nullptr, nullptr, ffb, Mrows, DFF, Dd, DFF);
    // 8. fc2 + residual
    gemm_tc<1><<<dim3(Dd/128, mtiles), 256, SMEM_NS>>>(
        ffb, wfc2T, b_fc2, x1, ls2, x2, nullptr, Mrows, Dd, DFF, Dd);
    // 9. fused cls -> gumbel -> top-k (adc = second output region)
    float* adc = out + (size_t)Bsz*(N_ALPHA+1)*Dd;
    score_kernel<<<Bsz, 608>>>(row0, selidx, adc);
    // 10. gather tokens
    gather_kernel<<<dim3(N_ALPHA+1, Bsz), 192>>>(x2, selidx, out);
}

// round 15
// speedup vs baseline: 1.0135x; 1.0135x over previous
#include <cuda_runtime.h>
#include <cuda_bf16.h>
#include <cstdint>

// Problem constants
#define Bsz 64
#define Nn  577
#define Dd  768
#define Hh  12
#define DH  64
#define DFF 3072
#define Mrows (Bsz*Nn)          // 36928
#define NUM_PATCHES 576
#define N_ALPHA 288
#define MC_SAMPLES 16
#define VSTR 640                // padded token stride for row0
#define PSTR 136                // bf16 P row stride (smem)

// ---------------- scratch (static device globals; no allocation) ------------
__device__ float g_x1 [(size_t)Mrows*Dd];
__device__ float g_x2 [(size_t)Mrows*Dd];
__device__ __nv_bfloat16 g_ah [(size_t)Mrows*Dd];      // LN1 out hi
__device__ __nv_bfloat16 g_al [(size_t)Mrows*Dd];      // LN1 out lo
__device__ __nv_bfloat16 g_qkvh[(size_t)Mrows*3*Dd];   // qkv result (bf16)
__device__ float g_row0[(size_t)Bsz*Hh*VSTR];          // raw cls scores per bh
__device__ float g_q0ex[(size_t)Bsz*Dd];               // exact fp32 q row 0 per batch
__device__ float g_wt  [(size_t)Bsz*Hh*Dd];            // w~ = Wk q0 per (b,h)
__device__ float g_c0  [Bsz*Hh];                       // q0 . bk per (b,h)
__device__ __nv_bfloat16 g_ob [(size_t)Mrows*Dd];      // attention out (bf16)
__device__ __nv_bfloat16 g_hb [(size_t)Mrows*Dd];      // LN2 out (bf16)
__device__ __nv_bfloat16 g_ffb[(size_t)Mrows*DFF];     // gelu(fc1) out (bf16)
__device__ __nv_bfloat16 g_wqkvT[(size_t)(3*Dd)*Dd];
__device__ __nv_bfloat16 g_wprojT[(size_t)Dd*Dd];
__device__ __nv_bfloat16 g_wfc1T [(size_t)DFF*Dd];
__device__ __nv_bfloat16 g_wfc2T [(size_t)Dd*DFF];
__device__ int   g_selidx[Bsz*N_ALPHA];

// ---------------- LayerNorm (bf16 out) and split hi/lo variant ---------------
__global__ __launch_bounds__(256) void ln_kernel_bf16(
    const float* __restrict__ x, const float* __restrict__ g,
    const float* __restrict__ be, __nv_bfloat16* __restrict__ out)
{
    int row  = blockIdx.x*8 + (threadIdx.x>>5);
    int lane = threadIdx.x & 31;
    if (row >= Mrows) return;
    const float4* xr = (const float4*)(x + (size_t)row*Dd);
    float4 v[6];
    float s = 0.f, sq = 0.f;
    #pragma unroll
    for (int i = 0; i < 6; i++) {
        v[i] = xr[lane + 32*i];
        s  += v[i].x + v[i].y + v[i].z + v[i].w;
        sq += v[i].x*v[i].x + v[i].y*v[i].y + v[i].z*v[i].z + v[i].w*v[i].w;
    }
    #pragma unroll
    for (int off = 16; off; off >>= 1) {
        s  += __shfl_xor_sync(0xffffffff, s,  off);
        sq += __shfl_xor_sync(0xffffffff, sq, off);
    }
    float mu  = s * (1.0f/Dd);
    float var = sq * (1.0f/Dd) - mu*mu;
    float rinv = rsqrtf(var + 1e-6f);
    const float4* gp = (const float4*)g;
    const float4* bp = (const float4*)be;
    __nv_bfloat162* op = (__nv_bfloat162*)(out + (size_t)row*Dd);
    #pragma unroll
    for (int i = 0; i < 6; i++) {
        int c = lane + 32*i;
        float4 gg = gp[c], bb = bp[c], vv = v[i];
        float r0 = (vv.x-mu)*rinv*gg.x + bb.x;
        float r1 = (vv.y-mu)*rinv*gg.y + bb.y;
        float r2 = (vv.z-mu)*rinv*gg.z + bb.z;
        float r3 = (vv.w-mu)*rinv*gg.w + bb.w;
        op[c*2+0] = __floats2bfloat162_rn(r0, r1);
        op[c*2+1] = __floats2bfloat162_rn(r2, r3);
    }
}

__global__ __launch_bounds__(256) void ln_split_kernel(
    const float* __restrict__ x, const float* __restrict__ g,
    const float* __restrict__ be,
    __nv_bfloat16* __restrict__ oh, __nv_bfloat16* __restrict__ ol)
{
    int row  = blockIdx.x*8 + (threadIdx.x>>5);
    int lane = threadIdx.x & 31;
    if (row >= Mrows) return;
    const float4* xr = (const float4*)(x + (size_t)row*Dd);
    float4 v[6];
    float s = 0.f, sq = 0.f;
    #pragma unroll
    for (int i = 0; i < 6; i++) {
        v[i] = xr[lane + 32*i];
        s  += v[i].x + v[i].y + v[i].z + v[i].w;
        sq += v[i].x*v[i].x + v[i].y*v[i].y + v[i].z*v[i].z + v[i].w*v[i].w;
    }
    #pragma unroll
    for (int off = 16; off; off >>= 1) {
        s  += __shfl_xor_sync(0xffffffff, s,  off);
        sq += __shfl_xor_sync(0xffffffff, sq, off);
    }
    float mu  = s * (1.0f/Dd);
    float var = sq * (1.0f/Dd) - mu*mu;
    float rinv = rsqrtf(var + 1e-6f);
    const float4* gp = (const float4*)g;
    const float4* bp = (const float4*)be;
    __nv_bfloat162* oph = (__nv_bfloat162*)(oh + (size_t)row*Dd);
    __nv_bfloat162* opl = (__nv_bfloat162*)(ol + (size_t)row*Dd);
    #pragma unroll
    for (int i = 0; i < 6; i++) {
        int c = lane + 32*i;
        float4 gg = gp[c], bb = bp[c], vv = v[i];
        float r[4];
        r[0] = (vv.x-mu)*rinv*gg.x + bb.x;
        r[1] = (vv.y-mu)*rinv*gg.y + bb.y;
        r[2] = (vv.z-mu)*rinv*gg.z + bb.z;
        r[3] = (vv.w-mu)*rinv*gg.w + bb.w;
        __nv_bfloat16 h0 = __float2bfloat16(r[0]);
        __nv_bfloat16 h1 = __float2bfloat16(r[1]);
        __nv_bfloat16 h2 = __float2bfloat16(r[2]);
        __nv_bfloat16 h3 = __float2bfloat16(r[3]);
        oph[c*2+0] = __nv_bfloat162(h0, h1);
        oph[c*2+1] = __nv_bfloat162(h2, h3);
        opl[c*2+0] = __floats2bfloat162_rn(r[0]-__bfloat162float(h0), r[1]-__bfloat162float(h1));
        opl[c*2+1] = __floats2bfloat162_rn(r[2]-__bfloat162float(h2), r[3]-__bfloat162float(h3));
    }
}

// ---------------- weight transpose: W[K][N] f32 -> Wt[N][K] bf16 -------------
__global__ void transpose_bf16_kernel(const float* __restrict__ W,
                                      __nv_bfloat16* __restrict__ Wt, int K, int N)
{
    __shared__ float tile[32][33];
    int k0 = blockIdx.y*32, n0 = blockIdx.x*32;
    int tx = threadIdx.x, ty = threadIdx.y;    // 32 x 8
    #pragma unroll
    for (int i = 0; i < 32; i += 8)
        tile[ty+i][tx] = W[(size_t)(k0+ty+i)*N + n0+tx];
    __syncthreads();
    #pragma unroll
    for (int i = 0; i < 32; i += 8)
        Wt[(size_t)(n0+ty+i)*K + k0+tx] = __float2bfloat16(tile[tx][ty+i]);
}

// ---------------- mma/ldmatrix helpers ----------------------------------------
__device__ __forceinline__ void mma16816(float* c, const uint32_t* a, const uint32_t* b) {
    asm volatile(
        "mma.sync.aligned.m16n8k16.row.col.f32.bf16.bf16.f32 "
        "{%0,%1,%2,%3}, {%4,%5,%6,%7}, {%8,%9}, {%0,%1,%2,%3};"
        : "+f"(c[0]), "+f"(c[1]), "+f"(c[2]), "+f"(c[3])
        : "r"(a[0]), "r"(a[1]), "r"(a[2]), "r"(a[3]), "r"(b[0]), "r"(b[1]));
}
__device__ __forceinline__ void ldsm4(uint32_t& r0, uint32_t& r1, uint32_t& r2, uint32_t& r3,
                                      uint32_t addr) {
    asm volatile("ldmatrix.sync.aligned.m8n8.x4.shared.b16 {%0,%1,%2,%3}, [%4];"
        : "=r"(r0), "=r"(r1), "=r"(r2), "=r"(r3) : "r"(addr));
}
__device__ __forceinline__ void ldsm4t(uint32_t& r0, uint32_t& r1, uint32_t& r2, uint32_t& r3,
                                       uint32_t addr) {
    asm volatile("ldmatrix.sync.aligned.m8n8.x4.trans.shared.b16 {%0,%1,%2,%3}, [%4];"
        : "=r"(r0), "=r"(r1), "=r"(r2), "=r"(r3) : "r"(addr));
}
__device__ __forceinline__ float tanh_fast(float x) {
    float r;
    asm("tanh.approx.f32 %0, %1;" : "=f"(r) : "f"(x));
    return r;
}

// ---------------- tensor-core GEMM 128x128 (3-stage cp.async) ----------------
// MODE 1: Cf = res + ls[n]*(acc + bias)          (fp32 out)
// MODE 2: Cb = gelu_tanh(acc + bias)             (bf16 out)
// MODE 4: Cb = bf16(acc + bias)                  (bf16 out)
#define TILE_H 8192   // halves per 128x64 tile (16KB)

template<int MODE>
__global__ __launch_bounds__(256) void gemm_tc(
    const __nv_bfloat16* __restrict__ A,
    const __nv_bfloat16* __restrict__ Bt,
    const float* __restrict__ bias, const float* __restrict__ res,
    const float* __restrict__ ls,
    float* __restrict__ Cf, __nv_bfloat16* __restrict__ Cb,
    int M, int N, int K, int ldc)
{
    extern __shared__ __nv_bfloat16 smem[];
    const int SS = 2*TILE_H;

    int m0 = blockIdx.y*128, n0 = blockIdx.x*128;
    int t = threadIdx.x;
    int warp = t >> 5, lane = t & 31;
    int wm = warp & 1, wn = warp >> 1;
    int g = lane >> 2, tq = lane & 3;

    float acc[4][4][4] = {};
    int KT = K >> 6;

    const int OFF_A = 0;
    const int OFF_B = TILE_H;

    auto load_tile = [&](__nv_bfloat16* dst, const __nv_bfloat16* src,
                         int row0, int k0, int rows_tot, int ld) {
        #pragma unroll
        for (int i = 0; i < 4; i++) {
            int chunk = t + i*256;
            int row = chunk >> 3;
            int kc  = chunk & 7;
            uint32_t sa = (uint32_t)__cvta_generic_to_shared(
                dst + row*64 + ((kc*8) ^ ((row&7)*8)));
            const __nv_bfloat16* gp = src + (size_t)(row0+row)*ld + k0 + kc*8;
            int sz = (row0+row < rows_tot) ? 16 : 0;
            asm volatile("cp.async.cg.shared.global [%0], [%1], 16, %2;\n"
                         :: "r"(sa), "l"(gp), "r"(sz));
        }
    };
    auto load_stage = [&](int buf, int kt) {
        int k0 = kt*64;
        __nv_bfloat16* st = smem + buf*SS;
        load_tile(st + OFF_A, A,  m0, k0, M, K);
        load_tile(st + OFF_B, Bt, n0, k0, N, K);
        asm volatile("cp.async.commit_group;\n");
    };

    int arow[4], abase[4], asw[4];
    #pragma unroll
    for (int mt = 0; mt < 4; mt++) {
        arow[mt]  = wm*64 + mt*16 + (lane & 15);
        abase[mt] = arow[mt]*128;
        asw[mt]   = (arow[mt] & 7) * 16;
    }
    int ahi = ((lane >> 4) & 1) * 16;
    int brow[2], bbase[2], bsw[2];
    #pragma unroll
    for (int np = 0; np < 2; np++) {
        brow[np]  = wn*32 + np*16 + ((lane >> 4) << 3) + (lane & 7);
        bbase[np] = brow[np]*128;
        bsw[np]   = (brow[np] & 7) * 16;
    }
    int bhi = ((lane >> 3) & 1) * 16;

    load_stage(0, 0);
    if (KT > 1) load_stage(1, 1);

    for (int kt = 0; kt < KT; kt++) {
        int buf = kt % 3;
        if (kt + 1 < KT) {
            asm volatile("cp.async.wait_group 1;\n");
        } else {
            asm volatile("cp.async.wait_group 0;\n");
        }
        __syncthreads();
        if (kt + 2 < KT) load_stage((kt + 2) % 3, kt + 2);

        uint32_t baseA = (uint32_t)__cvta_generic_to_shared(smem + buf*SS + OFF_A);
        uint32_t baseB = (uint32_t)__cvta_generic_to_shared(smem + buf*SS + OFF_B);

        #pragma unroll
        for (int ks = 0; ks < 4; ks++) {
            uint32_t ah[4][4], bh[2][4];
            #pragma unroll
            for (int mt = 0; mt < 4; mt++) {
                int off = abase[mt] + ((ks*32 + ahi) ^ asw[mt]);
                ldsm4(ah[mt][0], ah[mt][1], ah[mt][2], ah[mt][3], baseA + off);
            }
            #pragma unroll
            for (int np = 0; np < 2; np++) {
                int off = bbase[np] + ((ks*32 + bhi) ^ bsw[np]);
                ldsm4(bh[np][0], bh[np][1], bh[np][2], bh[np][3], baseB + off);
            }
            #pragma unroll
            for (int mt = 0; mt < 4; mt++)
                #pragma unroll
                for (int ni = 0; ni < 4; ni++)
                    mma16816(acc[mt][ni], ah[mt], &bh[ni>>1][(ni&1)*2]);
        }
    }

    #pragma unroll
    for (int mi = 0; mi < 4; mi++) {
        #pragma unroll
        for (int hh = 0; hh < 2; hh++) {
            int m = m0 + wm*64 + mi*16 + g + hh*8;
            if (m >= M) continue;
            #pragma unroll
            for (int ni = 0; ni < 4; ni++) {
                int n = n0 + wn*32 + ni*8 + tq*2;
                float v0 = acc[mi][ni][hh*2+0] + bias[n];
                float v1 = acc[mi][ni][hh*2+1] + bias[n+1];
                size_t o = (size_t)m*ldc + n;
                if (MODE == 1) {
                    Cf[o]   = res[o]   + ls[n]  *v0;
                    Cf[o+1] = res[o+1] + ls[n+1]*v1;
                } else if (MODE == 2) {
                    float c0 = 0.7978845608028654f*(v0 + 0.044715f*v0*v0*v0);
                    float c1 = 0.7978845608028654f*(v1 + 0.044715f*v1*v1*v1);
                    v0 = 0.5f*v0*(1.0f + tanh_fast(c0));
                    v1 = 0.5f*v1*(1.0f + tanh_fast(c1));
                    *(__nv_bfloat162*)(Cb + o) = __floats2bfloat162_rn(v0, v1);
                } else {
                    *(__nv_bfloat162*)(Cb + o) = __floats2bfloat162_rn(v0, v1);
                }
            }
        }
    }
}

// ---------------- exact fp32 q row-0 per batch: LN1(x[b,0]) @ Wq + bq ---------
__global__ __launch_bounds__(768) void q0exact_kernel(
    const float* __restrict__ x, const float* __restrict__ g,
    const float* __restrict__ be, const float* __restrict__ w_qkv,
    const float* __restrict__ b_qkv, float* __restrict__ q0ex)
{
    __shared__ float ln0[Dd];
    __shared__ float rs[24], rq[24];
    int b = blockIdx.x, t = threadIdx.x;
    int lane = t & 31, w = t >> 5;
    float v = x[(size_t)b*Nn*Dd + t];          // token 0
    float s = v, sq = v*v;
    #pragma unroll
    for (int off = 16; off; off >>= 1) {
        s  += __shfl_xor_sync(0xffffffff, s,  off);
        sq += __shfl_xor_sync(0xffffffff, sq, off);
    }
    if (lane == 0) { rs[w] = s; rq[w] = sq; }
    __syncthreads();
    if (t < 32) {
        float a = (t < 24) ? rs[t] : 0.f;
        float bb = (t < 24) ? rq[t] : 0.f;
        #pragma unroll
        for (int off = 16; off; off >>= 1) {
            a  += __shfl_xor_sync(0xffffffff, a,  off);
            bb += __shfl_xor_sync(0xffffffff, bb, off);
        }
        if (t == 0) { rs[0] = a; rq[0] = bb; }
    }
    __syncthreads();
    float mu = rs[0] * (1.0f/Dd);
    float var = rq[0] * (1.0f/Dd) - mu*mu;
    float rinv = rsqrtf(var + 1e-6f);
    ln0[t] = (v-mu)*rinv*g[t] + be[t];
    __syncthreads();
    float acc = b_qkv[t];                      // Q region col t
    #pragma unroll 8
    for (int k = 0; k < Dd; k++)
        acc += ln0[k] * w_qkv[(size_t)k*(3*Dd) + t];
    q0ex[(size_t)b*Dd + t] = acc;
}

// ---------------- w~ = Wk q0 per (b,h); c0 = q0 . bk --------------------------
__global__ __launch_bounds__(256) void wtilde_kernel(
    const float* __restrict__ w_qkv, const float* __restrict__ b_qkv,
    const float* __restrict__ q0ex, float* __restrict__ wt, float* __restrict__ c0g)
{
    __shared__ float q0s[64];
    int bh = blockIdx.x;
    int b = bh / Hh, h = bh - b*Hh;
    int t = threadIdx.x;
    if (t < 64) q0s[t] = q0ex[(size_t)b*Dd + h*DH + t];
    __syncthreads();
    #pragma unroll
    for (int i = 0; i < 3; i++) {
        int k = t + 256*i;
        const float* wr = w_qkv + (size_t)k*(3*Dd) + Dd + h*DH;
        float acc = 0.f;
        #pragma unroll
        for (int d = 0; d < 64; d++) acc += wr[d] * q0s[d];
        wt[(size_t)bh*Dd + k] = acc;
    }
    if (t == 0) {
        float c = 0.f;
        #pragma unroll
        for (int d = 0; d < 64; d++) c += q0s[d] * b_qkv[Dd + h*DH + d];
        c0g[bh] = c;
    }
}

// ---------------- row0: per (token-chunk, b) block, all heads in smem ---------
__global__ __launch_bounds__(512) void row0_kernel(
    const __nv_bfloat16* __restrict__ ah, const __nv_bfloat16* __restrict__ al,
    const float* __restrict__ wt, const float* __restrict__ c0g,
    float* __restrict__ row0g)
{
    __shared__ float ws[Hh*Dd];       // 36 KB
    __shared__ float c0s[Hh];
    int b = blockIdx.y, chunk = blockIdx.x;
    int t = threadIdx.x, lane = t & 31, w = t >> 5;   // 16 warps
    for (int i = t; i < Hh*Dd; i += 512)
        ws[i] = wt[(size_t)b*Hh*Dd + i];
    if (t < Hh) c0s[t] = c0g[b*Hh + t];
    __syncthreads();

    #pragma unroll
    for (int it = 0; it < 8; it++) {
        int tok = chunk*128 + it*16 + w;
        if (tok >= Nn) break;
        const __nv_bfloat162* ar = (const __nv_bfloat162*)(ah + ((size_t)(b*Nn + tok))*Dd);
        const __nv_bfloat162* lr = (const __nv_bfloat162*)(al + ((size_t)(b*Nn + tok))*Dd);
        float af[24];
        #pragma unroll
        for (int j = 0; j < 12; j++) {
            int k2 = lane + 32*j;
            __nv_bfloat162 a2 = ar[k2], l2 = lr[k2];
            af[2*j]   = __low2float(a2)  + __low2float(l2);
            af[2*j+1] = __high2float(a2) + __high2float(l2);
        }
        #pragma unroll
        for (int h = 0; h < Hh; h++) {
            const float* wsr = ws + h*Dd;
            float s = 0.f;
            #pragma unroll
            for (int j = 0; j < 12; j++) {
                int k2 = lane + 32*j;
                s += af[2*j]*wsr[2*k2] + af[2*j+1]*wsr[2*k2+1];
            }
            #pragma unroll
            for (int off = 16; off; off >>= 1) s += __shfl_xor_sync(0xffffffff, s, off);
            if (lane == 0)
                row0g[(size_t)(b*Hh + h)*VSTR + tok] = (s + c0s[h]) * 0.125f;
        }
    }
}

// ---------------- flash attention (no-max softmax, direct V, reg-exp) --------
__global__ __launch_bounds__(256) void fattn_kernel(
    const __nv_bfloat16* __restrict__ qkvh, __nv_bfloat16* __restrict__ ob)
{
    extern __shared__ __nv_bfloat16 sm[];
    __nv_bfloat16* Qh = sm;                  // 64*64
    __nv_bfloat16* Kh = Qh + 4096;           // 128*64
    __nv_bfloat16* Vh = Kh + 8192;           // 128*64 ([tok][d])
    __nv_bfloat16* Pm = Vh + 8192;           // 64*PSTR
    float* part = (float*)(Pm + 64*PSTR);    // [2][64] warp-partial row sums
    float* lsum = part + 128;                // [64] accumulated denominators

    int bh = blockIdx.y;
    int b = bh / Hh, h = bh - b*Hh;
    int q0 = blockIdx.x * 64;
    int t = threadIdx.x, lane = t & 31, warp = t >> 5;
    int wm = warp >> 1, wn = warp & 1;
    int g = lane >> 2, tq = lane & 3;

    const __nv_bfloat16* qsrc = qkvh + (size_t)b*Nn*(3*Dd) + h*DH;
    const __nv_bfloat16* ksrc = qsrc + Dd;
    const __nv_bfloat16* vsrc = qsrc + 2*Dd;

    auto ldt = [&](__nv_bfloat16* dst, const __nv_bfloat16* src,
                   int r0_, int rtot, int ld, int nrows) {
        int iters = nrows >> 5;
        for (int i = 0; i < iters; i++) {
            int chunk = t + i*256;
            int row = chunk >> 3;
            int kc  = chunk & 7;
            uint32_t sa = (uint32_t)__cvta_generic_to_shared(
                dst + row*64 + ((kc*8) ^ ((row&7)*8)));
            const __nv_bfloat16* gp = src + (size_t)(r0_+row)*ld + kc*8;
            int sz = (r0_+row < rtot) ? 16 : 0;
            asm volatile("cp.async.cg.shared.global [%0], [%1], 16, %2;\n"
                         :: "r"(sa), "l"(gp), "r"(sz));
        }
    };

    ldt(Qh, qsrc, q0, Nn, 3*Dd, 64);
    asm volatile("cp.async.commit_group;\n");

    if (t < 64) lsum[t] = 0.f;
    float acc_o[4][4] = {};

    int arowS = wm*16 + (lane & 15);
    int aswS  = (arowS & 7) * 16;
    int ahi   = ((lane >> 4) & 1) * 16;
    int bhi   = ((lane >> 3) & 1) * 16;
    int vrow_l = lane & 15;
    int vcol_l = ((lane >> 4) & 1) * 8;

    uint32_t baseQh = (uint32_t)__cvta_generic_to_shared(Qh);
    uint32_t baseKh = (uint32_t)__cvta_generic_to_shared(Kh);
    uint32_t baseVh = (uint32_t)__cvta_generic_to_shared(Vh);
    uint32_t basePm = (uint32_t)__cvta_generic_to_shared(Pm);

    const int NCHUNK = (Nn + 127) / 128;
    for (int c = 0; c < NCHUNK; c++) {
        int k0 = c*128;
        int limit = Nn - k0; if (limit > 128) limit = 128;

        __syncthreads();
        ldt(Kh, ksrc, k0, Nn, 3*Dd, 128);
        ldt(Vh, vsrc, k0, Nn, 3*Dd, 128);
        asm volatile("cp.async.commit_group;\n");
        asm volatile("cp.async.wait_group 0;\n");
        __syncthreads();

        // ---- S = Qh @ Kh^T ----
        float accs[8][4] = {};
        #pragma unroll
        for (int ks = 0; ks < 4; ks++) {
            uint32_t a4[4];
            int offA = arowS*128 + ((ks*32 + ahi) ^ aswS);
            ldsm4(a4[0], a4[1], a4[2], a4[3], baseQh + offA);
            uint32_t bh4[4][4];
            #pragma unroll
            for (int np = 0; np < 4; np++) {
                int brow = wn*64 + np*16 + ((lane >> 4) << 3) + (lane & 7);
                int offB = brow*128 + ((ks*32 + bhi) ^ ((brow&7)*16));
                ldsm4(bh4[np][0], bh4[np][1], bh4[np][2], bh4[np][3], baseKh + offB);
            }
            #pragma unroll
            for (int nf = 0; nf < 8; nf++)
                mma16816(accs[nf], a4, &bh4[nf>>1][(nf&1)*2]);
        }

        // ---- exp in registers -> P bf16 + per-row sums ----
        {
            int r0 = wm*16 + g, r1 = r0 + 8;
            float sum0 = 0.f, sum1 = 0.f;
            #pragma unroll
            for (int nf = 0; nf < 8; nf++) {
                int cc = wn*64 + nf*8 + tq*2;
                bool m0 = cc < limit, m1 = cc + 1 < limit;
                float e0 = m0 ? __expf(accs[nf][0]*0.125f) : 0.f;
                float e1 = m1 ? __expf(accs[nf][1]*0.125f) : 0.f;
                float e2 = m0 ? __expf(accs[nf][2]*0.125f) : 0.f;
                float e3 = m1 ? __expf(accs[nf][3]*0.125f) : 0.f;
                *(__nv_bfloat162*)(Pm + r0*PSTR + cc) = __floats2bfloat162_rn(e0, e1);
                *(__nv_bfloat162*)(Pm + r1*PSTR + cc) = __floats2bfloat162_rn(e2, e3);
                sum0 += e0 + e1;
                sum1 += e2 + e3;
            }
            sum0 += __shfl_xor_sync(0xffffffff, sum0, 1);
            sum0 += __shfl_xor_sync(0xffffffff, sum0, 2);
            sum1 += __shfl_xor_sync(0xffffffff, sum1, 1);
            sum1 += __shfl_xor_sync(0xffffffff, sum1, 2);
            if (tq == 0) { part[wn*64 + r0] = sum0; part[wn*64 + r1] = sum1; }
        }
        __syncthreads();
        if (t < 64) lsum[t] += part[t] + part[64 + t];

        // ---- O += P @ V (B fragments via trans ldmatrix on [tok][d]) ----
        {
            #pragma unroll
            for (int s = 0; s < 8; s++) {
                uint32_t a4[4];
                uint32_t offP = (uint32_t)((wm*16 + (lane & 15))*PSTR*2 + s*32 + ((lane>>4)&1)*16);
                ldsm4(a4[0], a4[1], a4[2], a4[3], basePm + offP);
                uint32_t bv[2][4];
                #pragma unroll
                for (int np = 0; np < 2; np++) {
                    int row = s*16 + vrow_l;
                    int col = wn*32 + np*16 + vcol_l;
                    int off = row*128 + ((col*2) ^ ((row&7)*16));
                    ldsm4t(bv[np][0], bv[np][1], bv[np][2], bv[np][3], baseVh + off);
                }
                #pragma unroll
                for (int nf = 0; nf < 4; nf++)
                    mma16816(acc_o[nf], a4, &bv[nf>>1][(nf&1)*2]);
            }
        }
    }

    __syncthreads();
    {
        int or0 = wm*16 + g, or1 = or0 + 8;
        float li0 = 1.f / lsum[or0];
        float li1 = 1.f / lsum[or1];
        int tok0 = q0 + or0, tok1 = q0 + or1;
        #pragma unroll
        for (int nf = 0; nf < 4; nf++) {
            int d = wn*32 + nf*8 + tq*2;
            if (tok0 < Nn)
                *(__nv_bfloat162*)(ob + ((size_t)(b*Nn + tok0))*Dd + h*DH + d) =
                    __floats2bfloat162_rn(acc_o[nf][0]*li0, acc_o[nf][1]*li0);
            if (tok1 < Nn)
                *(__nv_bfloat162*)(ob + ((size_t)(b*Nn + tok1))*Dd + h*DH + d) =
                    __floats2bfloat162_rn(acc_o[nf][2]*li1, acc_o[nf][3]*li1);
        }
    }
}

// ---------------- threefry2x32 for jax.random.key(42) ------------------------
__device__ __forceinline__ void tf_round(unsigned& x0, unsigned& x1, int r) {
    x0 += x1;
    x1 = ((x1 << r) | (x1 >> (32 - r))) ^ x0;
}
__device__ __forceinline__ uint2 threefry_42(unsigned c0, unsigned c1) {
    const unsigned k0 = 0u, k1 = 42u, k2 = 0x1BD11BDAu ^ 42u;
    unsigned x0 = c0 + k0, x1 = c1 + k1;
    tf_round(x0,x1,13); tf_round(x0,x1,15); tf_round(x0,x1,26); tf_round(x0,x1,6);
    x0 += k1; x1 += k2 + 1u;
    tf_round(x0,x1,17); tf_round(x0,x1,29); tf_round(x0,x1,16); tf_round(x0,x1,24);
    x0 += k2; x1 += k0 + 2u;
    tf_round(x0,x1,13); tf_round(x0,x1,15); tf_round(x0,x1,26); tf_round(x0,x1,6);
    x0 += k0; x1 += k1 + 3u;
    tf_round(x0,x1,17); tf_round(x0,x1,29); tf_round(x0,x1,16); tf_round(x0,x1,24);
    x0 += k1; x1 += k2 + 4u;
    tf_round(x0,x1,13); tf_round(x0,x1,15); tf_round(x0,x1,26); tf_round(x0,x1,6);
    x0 += k2; x1 += k0 + 5u;
    return make_uint2(x0, x1);
}

// ---------------- fused scoring: cls softmax-mean -> gumbel MC -> top-k -------
__global__ __launch_bounds__(608) void score_kernel(
    const float* __restrict__ row0g, int* __restrict__ selidx, float* __restrict__ adc)
{
    __shared__ float red[19];
    __shared__ float bcast;
    __shared__ float logit_sm[NUM_PATCHES];
    __shared__ float s_sm[NUM_PATCHES];
    __shared__ int flags[NUM_PATCHES];
    int b = blockIdx.x, t = threadIdx.x;
    int lane = t & 31, w = t >> 5;

    // phase 1: cls attention row, softmax per head, mean over heads
    float acc = 0.f;
    for (int h = 0; h < Hh; h++) {
        float s = (t < Nn) ? row0g[((size_t)(b*Hh + h))*VSTR + t] : -1e30f;
        float m = s;
        #pragma unroll
        for (int off = 16; off; off >>= 1) m = fmaxf(m, __shfl_xor_sync(0xffffffff, m, off));
        if (lane == 0) red[w] = m;
        __syncthreads();
        if (t == 0) {
            float mm = red[0];
            for (int i = 1; i < 19; i++) mm = fmaxf(mm, red[i]);
            bcast = mm;
        }
        __syncthreads();
        float M = bcast;
        float e = (t < Nn) ? expf(s - M) : 0.f;
        float sv = e;
        #pragma unroll
        for (int off = 16; off; off >>= 1) sv += __shfl_xor_sync(0xffffffff, sv, off);
        if (lane == 0) red[w] = sv;
        __syncthreads();
        if (t == 0) {
            float ss = 0.f;
            for (int i = 0; i < 19; i++) ss += red[i];
            bcast = ss;
        }
        __syncthreads();
        acc += e / bcast;
        __syncthreads();
    }
    if (t >= 1 && t < Nn) logit_sm[t-1] = logf(acc*(1.0f/Hh) + 1e-8f);
    __syncthreads();

    // phase 2: gumbel MC softmax (patch p = t for t < 576)
    float lg = (t < NUM_PATCHES) ? logit_sm[t] : -1e30f;
    float sacc = 0.f;
    for (int s = 0; s < MC_SAMPLES; s++) {
        float tt = -1e30f;
        if (t < NUM_PATCHES) {
            unsigned i = (unsigned)((s*Bsz + b)*NUM_PATCHES + t);
            uint2 r = threefry_42(0u, i);
            unsigned bits = r.x ^ r.y;
            float f = __uint_as_float(0x3f800000u | (bits >> 9)) - 1.0f;
            const float mn = 1e-6f, mx = 1.0f - 1e-6f;
            float u = fmaxf(f*(mx - mn) + mn, mn);
            float g = -logf(-logf(u));
            tt = (lg + g) * 2.0f;
        }
        float m = tt;
        #pragma unroll
        for (int off = 16; off; off >>= 1) m = fmaxf(m, __shfl_xor_sync(0xffffffff, m, off));
        if (lane == 0) red[w] = m;
        __syncthreads();
        if (t == 0) {
            float mm = red[0];
            for (int i = 1; i < 19; i++) mm = fmaxf(mm, red[i]);
            bcast = mm;
        }
        __syncthreads();
        float e = (t < NUM_PATCHES) ? expf(tt - bcast) : 0.f;
        __syncthreads();
        float sv = e;
        #pragma unroll
        for (int off = 16; off; off >>= 1) sv += __shfl_xor_sync(0xffffffff, sv, off);
        if (lane == 0) red[w] = sv;
        __syncthreads();
        if (t == 0) {
            float ss = 0.f;
            for (int i = 0; i < 19; i++) ss += red[i];
            bcast = ss;
        }
        __syncthreads();
        sacc += e / bcast;
        __syncthreads();
    }
    if (t < NUM_PATCHES) s_sm[t] = sacc * (1.0f/MC_SAMPLES);
    __syncthreads();

    // phase 3: stable top-k(288) + outputs
    if (t < NUM_PATCHES) {
        float sp = s_sm[t];
        int rank = 0;
        for (int j = 0; j < NUM_PATCHES; j++) {
            float sj = s_sm[j];
            rank += (sj > sp) || (sj == sp && j < t);
        }
        flags[t] = (rank < N_ALPHA) ? 1 : 0;
    }
    __syncthreads();
    if (t < NUM_PATCHES && flags[t]) {
        int pos = 0;
        for (int j = 0; j < t; j++) pos += flags[j];
        selidx[b*N_ALPHA + pos] = t + 1;
        adc[(size_t)b*(N_ALPHA+1) + pos + 1] = s_sm[t];
    }
    if (t == 0) adc[(size_t)b*(N_ALPHA+1)] = 1.0f;
}

// ---------------- gather selected tokens --------------------------------------
__global__ void gather_kernel(const float* __restrict__ x2,
                              const int* __restrict__ selidx, float* __restrict__ out)
{
    int j = blockIdx.x;
    int b = blockIdx.y;
    int row = (j == 0) ? 0 : selidx[b*N_ALPHA + j - 1];
    const float4* src = (const float4*)(x2 + ((size_t)b*Nn + row)*Dd);
    float4* dst = (float4*)(out + ((size_t)b*(N_ALPHA+1) + j)*Dd);
    dst[threadIdx.x] = src[threadIdx.x];
}

// ---------------- launch -------------------------------------------------------
extern "C" void kernel_launch(void* const* d_in, const int* in_sizes, int n_in,
                              void* d_out, int out_size)
{
    const float* x      = (const float*)d_in[0];
    const float* g1     = (const float*)d_in[1];
    const float* b1     = (const float*)d_in[2];
    const float* w_qkv  = (const float*)d_in[3];
    const float* b_qkv  = (const float*)d_in[4];
    const float* w_proj = (const float*)d_in[5];
    const float* b_proj = (const float*)d_in[6];
    const float* ls1    = (const float*)d_in[7];
    const float* g2     = (const float*)d_in[8];
    const float* b2     = (const float*)d_in[9];
    const float* w_fc1  = (const float*)d_in[10];
    const float* b_fc1  = (const float*)d_in[11];
    const float* w_fc2  = (const float*)d_in[12];
    const float* b_fc2  = (const float*)d_in[13];
    const float* ls2    = (const float*)d_in[14];
    float* out = (float*)d_out;

    float *x1, *x2, *row0, *q0ex, *wt, *c0;
    __nv_bfloat16 *ah, *al, *qkvh, *ob, *hb, *ffb;
    __nv_bfloat16 *wqkvT, *wprojT, *wfc1T, *wfc2T;
    int* selidx;
    cudaGetSymbolAddress((void**)&x1,     g_x1);
    cudaGetSymbolAddress((void**)&x2,     g_x2);
    cudaGetSymbolAddress((void**)&ah,     g_ah);
    cudaGetSymbolAddress((void**)&al,     g_al);
    cudaGetSymbolAddress((void**)&qkvh,   g_qkvh);
    cudaGetSymbolAddress((void**)&row0,   g_row0);
    cudaGetSymbolAddress((void**)&q0ex,   g_q0ex);
    cudaGetSymbolAddress((void**)&wt,     g_wt);
    cudaGetSymbolAddress((void**)&c0,     g_c0);
    cudaGetSymbolAddress((void**)&ob,     g_ob);
    cudaGetSymbolAddress((void**)&hb,     g_hb);
    cudaGetSymbolAddress((void**)&ffb,    g_ffb);
    cudaGetSymbolAddress((void**)&wqkvT,  g_wqkvT);
    cudaGetSymbolAddress((void**)&wprojT, g_wprojT);
    cudaGetSymbolAddress((void**)&wfc1T,  g_wfc1T);
    cudaGetSymbolAddress((void**)&wfc2T,  g_wfc2T);
    cudaGetSymbolAddress((void**)&selidx, g_selidx);

    int mblk = (Mrows + 7) / 8;
    int mtiles = (Mrows + 127) / 128;           // 289

    const int SMEM_NS = 3*2*TILE_H*2;           // 96KB (3 stages)
    cudaFuncSetAttribute(gemm_tc<4>, cudaFuncAttributeMaxDynamicSharedMemorySize, SMEM_NS);
    cudaFuncSetAttribute(gemm_tc<1>, cudaFuncAttributeMaxDynamicSharedMemorySize, SMEM_NS);
    cudaFuncSetAttribute(gemm_tc<2>, cudaFuncAttributeMaxDynamicSharedMemorySize, SMEM_NS);

    const int ATTN_SMEM = (4096+8192+8192+64*PSTR)*2 + (128+64)*4;
    cudaFuncSetAttribute(fattn_kernel, cudaFuncAttributeMaxDynamicSharedMemorySize, ATTN_SMEM);

    // 0. weight transposes
    transpose_bf16_kernel<<<dim3(3*Dd/32, Dd/32), dim3(32,8)>>>(w_qkv, wqkvT, Dd, 3*Dd);
    transpose_bf16_kernel<<<dim3(Dd/32,  Dd/32),  dim3(32,8)>>>(w_proj, wprojT, Dd,  Dd);
    transpose_bf16_kernel<<<dim3(DFF/32, Dd/32),  dim3(32,8)>>>(w_fc1,  wfc1T,  Dd,  DFF);
    transpose_bf16_kernel<<<dim3(Dd/32,  DFF/32), dim3(32,8)>>>(w_fc2,  wfc2T,  DFF, Dd);
    // 0b. exact q0 + w~ (selection-critical path, fp32 end-to-end)
    q0exact_kernel<<<Bsz, 768>>>(x, g1, b1, w_qkv, b_qkv, q0ex);
    wtilde_kernel<<<Bsz*Hh, 256>>>(w_qkv, b_qkv, q0ex, wt, c0);

    // 1. LN1 (split hi/lo bf16)
    ln_split_kernel<<<mblk, 256>>>(x, g1, b1, ah, al);
    // 2. QKV GEMM (N = 2304)
    gemm_tc<4><<<dim3(3*Dd/128, mtiles), 256, SMEM_NS>>>(
        ah, wqkvT, b_qkv, nullptr, nullptr, nullptr, qkvh, Mrows, 3*Dd, Dd, 3*Dd);
    // 3. cls-row scores (all heads per block; one pass over ah/al)
    row0_kernel<<<dim3((Nn+127)/128, Bsz), 512>>>(ah, al, wt, c0, row0);
    // 4. flash attention (direct V, in-register softmax)
    fattn_kernel<<<dim3((Nn+63)/64, Bsz*Hh), 256, ATTN_SMEM>>>(qkvh, ob);
    // 5. proj + residual
    gemm_tc<1><<<dim3(Dd/128, mtiles), 256, SMEM_NS>>>(
        ob, wprojT, b_proj, x, ls1, x1, nullptr, Mrows, Dd, Dd, Dd);
    // 6. LN2 (bf16 out)
    ln_kernel_bf16<<<mblk, 256>>>(x1, g2, b2, hb);
    // 7. fc1 + gelu (tanh.approx)
    gemm_tc<2><<<dim3(DFF/128, mtiles), 256, SMEM_NS>>>(
        hb, wfc1T, b_fc1, nullptr, nullptr, nullptr, ffb, Mrows, DFF, Dd, DFF);
    // 8. fc2 + residual
    gemm_tc<1><<<dim3(Dd/128, mtiles), 256, SMEM_NS>>>(
        ffb, wfc2T, b_fc2, x1, ls2, x2, nullptr, Mrows, Dd, DFF, Dd);
    // 9. fused cls -> gumbel -> top-k (adc = second output region)
    float* adc = out + (size_t)Bsz*(N_ALPHA+1)*Dd;
    score_kernel<<<Bsz, 608>>>(row0, selidx, adc);
    // 10. gather tokens
    gather_kernel<<<dim3(N_ALPHA+1, Bsz), 192>>>(x2, selidx, out);
}

// round 16
// speedup vs baseline: 1.0196x; 1.0060x over previous
#include <cuda_runtime.h>
#include <cuda_bf16.h>
#include <cstdint>

// Problem constants
#define Bsz 64
#define Nn  577
#define Dd  768
#define Hh  12
#define DH  64
#define DFF 3072
#define Mrows (Bsz*Nn)          // 36928
#define NUM_PATCHES 576
#define N_ALPHA 288
#define MC_SAMPLES 16
#define VSTR 640                // padded token stride for row0
#define PSTR 136                // bf16 P row stride (smem)

// ---------------- scratch (static device globals; no allocation) ------------
__device__ float g_x1 [(size_t)Mrows*Dd];
__device__ float g_x2 [(size_t)Mrows*Dd];
__device__ __nv_bfloat16 g_ah [(size_t)Mrows*Dd];      // LN1 out hi
__device__ __nv_bfloat16 g_al [(size_t)Mrows*Dd];      // LN1 out lo
__device__ __nv_bfloat16 g_qkvh[(size_t)Mrows*3*Dd];   // qkv result (bf16)
__device__ float g_row0[(size_t)Bsz*Hh*VSTR];          // raw cls scores per bh
__device__ float g_q0ex[(size_t)Bsz*Dd];               // exact fp32 q row 0 per batch
__device__ float g_wt  [(size_t)Bsz*Hh*Dd];            // w~ = Wk q0 per (b,h)
__device__ float g_c0  [Bsz*Hh];                       // q0 . bk per (b,h)
__device__ __nv_bfloat16 g_ob [(size_t)Mrows*Dd];      // attention out (bf16)
__device__ __nv_bfloat16 g_hb [(size_t)Mrows*Dd];      // LN2 out (bf16)
__device__ __nv_bfloat16 g_ffb[(size_t)Mrows*DFF];     // gelu(fc1) out (bf16)
__device__ __nv_bfloat16 g_wqkvT[(size_t)(3*Dd)*Dd];
__device__ __nv_bfloat16 g_wprojT[(size_t)Dd*Dd];
__device__ __nv_bfloat16 g_wfc1T [(size_t)DFF*Dd];
__device__ __nv_bfloat16 g_wfc2T [(size_t)Dd*DFF];
__device__ int   g_selidx[Bsz*N_ALPHA];

// ---------------- LayerNorm (bf16 out) and split hi/lo variant ---------------
__global__ __launch_bounds__(256) void ln_kernel_bf16(
    const float* __restrict__ x, const float* __restrict__ g,
    const float* __restrict__ be, __nv_bfloat16* __restrict__ out)
{
    int row  = blockIdx.x*8 + (threadIdx.x>>5);
    int lane = threadIdx.x & 31;
    if (row >= Mrows) return;
    const float4* xr = (const float4*)(x + (size_t)row*Dd);
    float4 v[6];
    float s = 0.f, sq = 0.f;
    #pragma unroll
    for (int i = 0; i < 6; i++) {
        v[i] = xr[lane + 32*i];
        s  += v[i].x + v[i].y + v[i].z + v[i].w;
        sq += v[i].x*v[i].x + v[i].y*v[i].y + v[i].z*v[i].z + v[i].w*v[i].w;
    }
    #pragma unroll
    for (int off = 16; off; off >>= 1) {
        s  += __shfl_xor_sync(0xffffffff, s,  off);
        sq += __shfl_xor_sync(0xffffffff, sq, off);
    }
    float mu  = s * (1.0f/Dd);
    float var = sq * (1.0f/Dd) - mu*mu;
    float rinv = rsqrtf(var + 1e-6f);
    const float4* gp = (const float4*)g;
    const float4* bp = (const float4*)be;
    __nv_bfloat162* op = (__nv_bfloat162*)(out + (size_t)row*Dd);
    #pragma unroll
    for (int i = 0; i < 6; i++) {
        int c = lane + 32*i;
        float4 gg = gp[c], bb = bp[c], vv = v[i];
        float r0 = (vv.x-mu)*rinv*gg.x + bb.x;
        float r1 = (vv.y-mu)*rinv*gg.y + bb.y;
        float r2 = (vv.z-mu)*rinv*gg.z + bb.z;
        float r3 = (vv.w-mu)*rinv*gg.w + bb.w;
        op[c*2+0] = __floats2bfloat162_rn(r0, r1);
        op[c*2+1] = __floats2bfloat162_rn(r2, r3);
    }
}

__global__ __launch_bounds__(256) void ln_split_kernel(
    const float* __restrict__ x, const float* __restrict__ g,
    const float* __restrict__ be,
    __nv_bfloat16* __restrict__ oh, __nv_bfloat16* __restrict__ ol)
{
    int row  = blockIdx.x*8 + (threadIdx.x>>5);
    int lane = threadIdx.x & 31;
    if (row >= Mrows) return;
    const float4* xr = (const float4*)(x + (size_t)row*Dd);
    float4 v[6];
    float s = 0.f, sq = 0.f;
    #pragma unroll
    for (int i = 0; i < 6; i++) {
        v[i] = xr[lane + 32*i];
        s  += v[i].x + v[i].y + v[i].z + v[i].w;
        sq += v[i].x*v[i].x + v[i].y*v[i].y + v[i].z*v[i].z + v[i].w*v[i].w;
    }
    #pragma unroll
    for (int off = 16; off; off >>= 1) {
        s  += __shfl_xor_sync(0xffffffff, s,  off);
        sq += __shfl_xor_sync(0xffffffff, sq, off);
    }
    float mu  = s * (1.0f/Dd);
    float var = sq * (1.0f/Dd) - mu*mu;
    float rinv = rsqrtf(var + 1e-6f);
    const float4* gp = (const float4*)g;
    const float4* bp = (const float4*)be;
    __nv_bfloat162* oph = (__nv_bfloat162*)(oh + (size_t)row*Dd);
    __nv_bfloat162* opl = (__nv_bfloat162*)(ol + (size_t)row*Dd);
    #pragma unroll
    for (int i = 0; i < 6; i++) {
        int c = lane + 32*i;
        float4 gg = gp[c], bb = bp[c], vv = v[i];
        float r[4];
        r[0] = (vv.x-mu)*rinv*gg.x + bb.x;
        r[1] = (vv.y-mu)*rinv*gg.y + bb.y;
        r[2] = (vv.z-mu)*rinv*gg.z + bb.z;
        r[3] = (vv.w-mu)*rinv*gg.w + bb.w;
        __nv_bfloat16 h0 = __float2bfloat16(r[0]);
        __nv_bfloat16 h1 = __float2bfloat16(r[1]);
        __nv_bfloat16 h2 = __float2bfloat16(r[2]);
        __nv_bfloat16 h3 = __float2bfloat16(r[3]);
        oph[c*2+0] = __nv_bfloat162(h0, h1);
        oph[c*2+1] = __nv_bfloat162(h2, h3);
        opl[c*2+0] = __floats2bfloat162_rn(r[0]-__bfloat162float(h0), r[1]-__bfloat162float(h1));
        opl[c*2+1] = __floats2bfloat162_rn(r[2]-__bfloat162float(h2), r[3]-__bfloat162float(h3));
    }
}

// ---------------- weight transpose: W[K][N] f32 -> Wt[N][K] bf16 -------------
__global__ void transpose_bf16_kernel(const float* __restrict__ W,
                                      __nv_bfloat16* __restrict__ Wt, int K, int N)
{
    __shared__ float tile[32][33];
    int k0 = blockIdx.y*32, n0 = blockIdx.x*32;
    int tx = threadIdx.x, ty = threadIdx.y;    // 32 x 8
    #pragma unroll
    for (int i = 0; i < 32; i += 8)
        tile[ty+i][tx] = W[(size_t)(k0+ty+i)*N + n0+tx];
    __syncthreads();
    #pragma unroll
    for (int i = 0; i < 32; i += 8)
        Wt[(size_t)(n0+ty+i)*K + k0+tx] = __float2bfloat16(tile[tx][ty+i]);
}

// ---------------- mma/ldmatrix helpers ----------------------------------------
__device__ __forceinline__ void mma16816(float* c, const uint32_t* a, const uint32_t* b) {
    asm volatile(
        "mma.sync.aligned.m16n8k16.row.col.f32.bf16.bf16.f32 "
        "{%0,%1,%2,%3}, {%4,%5,%6,%7}, {%8,%9}, {%0,%1,%2,%3};"
        : "+f"(c[0]), "+f"(c[1]), "+f"(c[2]), "+f"(c[3])
        : "r"(a[0]), "r"(a[1]), "r"(a[2]), "r"(a[3]), "r"(b[0]), "r"(b[1]));
}
__device__ __forceinline__ void ldsm4(uint32_t& r0, uint32_t& r1, uint32_t& r2, uint32_t& r3,
                                      uint32_t addr) {
    asm volatile("ldmatrix.sync.aligned.m8n8.x4.shared.b16 {%0,%1,%2,%3}, [%4];"
        : "=r"(r0), "=r"(r1), "=r"(r2), "=r"(r3) : "r"(addr));
}
__device__ __forceinline__ void ldsm4t(uint32_t& r0, uint32_t& r1, uint32_t& r2, uint32_t& r3,
                                       uint32_t addr) {
    asm volatile("ldmatrix.sync.aligned.m8n8.x4.trans.shared.b16 {%0,%1,%2,%3}, [%4];"
        : "=r"(r0), "=r"(r1), "=r"(r2), "=r"(r3) : "r"(addr));
}
__device__ __forceinline__ float tanh_fast(float x) {
    float r;
    asm("tanh.approx.f32 %0, %1;" : "=f"(r) : "f"(x));
    return r;
}

// ---------------- tensor-core GEMM 128x128 (3-stage cp.async) ----------------
// MODE 1: Cf = res + ls[n]*(acc + bias)          (fp32 out)
// MODE 2: Cb = gelu_tanh(acc + bias)             (bf16 out)
// MODE 4: Cb = bf16(acc + bias)                  (bf16 out)
#define TILE_H 8192   // halves per 128x64 tile (16KB)

template<int MODE>
__global__ __launch_bounds__(256) void gemm_tc(
    const __nv_bfloat16* __restrict__ A,
    const __nv_bfloat16* __restrict__ Bt,
    const float* __restrict__ bias, const float* __restrict__ res,
    const float* __restrict__ ls,
    float* __restrict__ Cf, __nv_bfloat16* __restrict__ Cb,
    int M, int N, int K, int ldc)
{
    extern __shared__ __nv_bfloat16 smem[];
    const int SS = 2*TILE_H;

    int m0 = blockIdx.y*128, n0 = blockIdx.x*128;
    int t = threadIdx.x;
    int warp = t >> 5, lane = t & 31;
    int wm = warp & 1, wn = warp >> 1;
    int g = lane >> 2, tq = lane & 3;

    float acc[4][4][4] = {};
    int KT = K >> 6;

    const int OFF_A = 0;
    const int OFF_B = TILE_H;

    auto load_tile = [&](__nv_bfloat16* dst, const __nv_bfloat16* src,
                         int row0, int k0, int rows_tot, int ld) {
        #pragma unroll
        for (int i = 0; i < 4; i++) {
            int chunk = t + i*256;
            int row = chunk >> 3;
            int kc  = chunk & 7;
            uint32_t sa = (uint32_t)__cvta_generic_to_shared(
                dst + row*64 + ((kc*8) ^ ((row&7)*8)));
            const __nv_bfloat16* gp = src + (size_t)(row0+row)*ld + k0 + kc*8;
            int sz = (row0+row < rows_tot) ? 16 : 0;
            asm volatile("cp.async.cg.shared.global [%0], [%1], 16, %2;\n"
                         :: "r"(sa), "l"(gp), "r"(sz));
        }
    };
    auto load_stage = [&](int buf, int kt) {
        int k0 = kt*64;
        __nv_bfloat16* st = smem + buf*SS;
        load_tile(st + OFF_A, A,  m0, k0, M, K);
        load_tile(st + OFF_B, Bt, n0, k0, N, K);
        asm volatile("cp.async.commit_group;\n");
    };

    int arow[4], abase[4], asw[4];
    #pragma unroll
    for (int mt = 0; mt < 4; mt++) {
        arow[mt]  = wm*64 + mt*16 + (lane & 15);
        abase[mt] = arow[mt]*128;
        asw[mt]   = (arow[mt] & 7) * 16;
    }
    int ahi = ((lane >> 4) & 1) * 16;
    int brow[2], bbase[2], bsw[2];
    #pragma unroll
    for (int np = 0; np < 2; np++) {
        brow[np]  = wn*32 + np*16 + ((lane >> 4) << 3) + (lane & 7);
        bbase[np] = brow[np]*128;
        bsw[np]   = (brow[np] & 7) * 16;
    }
    int bhi = ((lane >> 3) & 1) * 16;

    load_stage(0, 0);
    if (KT > 1) load_stage(1, 1);

    for (int kt = 0; kt < KT; kt++) {
        int buf = kt % 3;
        if (kt + 1 < KT) {
            asm volatile("cp.async.wait_group 1;\n");
        } else {
            asm volatile("cp.async.wait_group 0;\n");
        }
        __syncthreads();
        if (kt + 2 < KT) load_stage((kt + 2) % 3, kt + 2);

        uint32_t baseA = (uint32_t)__cvta_generic_to_shared(smem + buf*SS + OFF_A);
        uint32_t baseB = (uint32_t)__cvta_generic_to_shared(smem + buf*SS + OFF_B);

        #pragma unroll
        for (int ks = 0; ks < 4; ks++) {
            uint32_t ah[4][4], bh[2][4];
            #pragma unroll
            for (int mt = 0; mt < 4; mt++) {
                int off = abase[mt] + ((ks*32 + ahi) ^ asw[mt]);
                ldsm4(ah[mt][0], ah[mt][1], ah[mt][2], ah[mt][3], baseA + off);
            }
            #pragma unroll
            for (int np = 0; np < 2; np++) {
                int off = bbase[np] + ((ks*32 + bhi) ^ bsw[np]);
                ldsm4(bh[np][0], bh[np][1], bh[np][2], bh[np][3], baseB + off);
            }
            #pragma unroll
            for (int mt = 0; mt < 4; mt++)
                #pragma unroll
                for (int ni = 0; ni < 4; ni++)
                    mma16816(acc[mt][ni], ah[mt], &bh[ni>>1][(ni&1)*2]);
        }
    }

    #pragma unroll
    for (int mi = 0; mi < 4; mi++) {
        #pragma unroll
        for (int hh = 0; hh < 2; hh++) {
            int m = m0 + wm*64 + mi*16 + g + hh*8;
            if (m >= M) continue;
            #pragma unroll
            for (int ni = 0; ni < 4; ni++) {
                int n = n0 + wn*32 + ni*8 + tq*2;
                float v0 = acc[mi][ni][hh*2+0] + bias[n];
                float v1 = acc[mi][ni][hh*2+1] + bias[n+1];
                size_t o = (size_t)m*ldc + n;
                if (MODE == 1) {
                    Cf[o]   = res[o]   + ls[n]  *v0;
                    Cf[o+1] = res[o+1] + ls[n+1]*v1;
                } else if (MODE == 2) {
                    float c0 = 0.7978845608028654f*(v0 + 0.044715f*v0*v0*v0);
                    float c1 = 0.7978845608028654f*(v1 + 0.044715f*v1*v1*v1);
                    v0 = 0.5f*v0*(1.0f + tanh_fast(c0));
                    v1 = 0.5f*v1*(1.0f + tanh_fast(c1));
                    *(__nv_bfloat162*)(Cb + o) = __floats2bfloat162_rn(v0, v1);
                } else {
                    *(__nv_bfloat162*)(Cb + o) = __floats2bfloat162_rn(v0, v1);
                }
            }
        }
    }
}

// ---------------- exact fp32 q row-0 per batch: LN1(x[b,0]) @ Wq + bq ---------
__global__ __launch_bounds__(768) void q0exact_kernel(
    const float* __restrict__ x, const float* __restrict__ g,
    const float* __restrict__ be, const float* __restrict__ w_qkv,
    const float* __restrict__ b_qkv, float* __restrict__ q0ex)
{
    __shared__ float ln0[Dd];
    __shared__ float rs[24], rq[24];
    int b = blockIdx.x, t = threadIdx.x;
    int lane = t & 31, w = t >> 5;
    float v = x[(size_t)b*Nn*Dd + t];          // token 0
    float s = v, sq = v*v;
    #pragma unroll
    for (int off = 16; off; off >>= 1) {
        s  += __shfl_xor_sync(0xffffffff, s,  off);
        sq += __shfl_xor_sync(0xffffffff, sq, off);
    }
    if (lane == 0) { rs[w] = s; rq[w] = sq; }
    __syncthreads();
    if (t < 32) {
        float a = (t < 24) ? rs[t] : 0.f;
        float bb = (t < 24) ? rq[t] : 0.f;
        #pragma unroll
        for (int off = 16; off; off >>= 1) {
            a  += __shfl_xor_sync(0xffffffff, a,  off);
            bb += __shfl_xor_sync(0xffffffff, bb, off);
        }
        if (t == 0) { rs[0] = a; rq[0] = bb; }
    }
    __syncthreads();
    float mu = rs[0] * (1.0f/Dd);
    float var = rq[0] * (1.0f/Dd) - mu*mu;
    float rinv = rsqrtf(var + 1e-6f);
    ln0[t] = (v-mu)*rinv*g[t] + be[t];
    __syncthreads();
    float acc = b_qkv[t];                      // Q region col t
    #pragma unroll 8
    for (int k = 0; k < Dd; k++)
        acc += ln0[k] * w_qkv[(size_t)k*(3*Dd) + t];
    q0ex[(size_t)b*Dd + t] = acc;
}

// ---------------- w~ = Wk q0 per (b,h); c0 = q0 . bk --------------------------
__global__ __launch_bounds__(256) void wtilde_kernel(
    const float* __restrict__ w_qkv, const float* __restrict__ b_qkv,
    const float* __restrict__ q0ex, float* __restrict__ wt, float* __restrict__ c0g)
{
    __shared__ float q0s[64];
    int bh = blockIdx.x;
    int b = bh / Hh, h = bh - b*Hh;
    int t = threadIdx.x;
    if (t < 64) q0s[t] = q0ex[(size_t)b*Dd + h*DH + t];
    __syncthreads();
    #pragma unroll
    for (int i = 0; i < 3; i++) {
        int k = t + 256*i;
        const float* wr = w_qkv + (size_t)k*(3*Dd) + Dd + h*DH;
        float acc = 0.f;
        #pragma unroll
        for (int d = 0; d < 64; d++) acc += wr[d] * q0s[d];
        wt[(size_t)bh*Dd + k] = acc;
    }
    if (t == 0) {
        float c = 0.f;
        #pragma unroll
        for (int d = 0; d < 64; d++) c += q0s[d] * b_qkv[Dd + h*DH + d];
        c0g[bh] = c;
    }
}

// ---------------- row0: per (token-chunk, b) block, all heads in smem ---------
__global__ __launch_bounds__(512) void row0_kernel(
    const __nv_bfloat16* __restrict__ ah, const __nv_bfloat16* __restrict__ al,
    const float* __restrict__ wt, const float* __restrict__ c0g,
    float* __restrict__ row0g)
{
    __shared__ float ws[Hh*Dd];       // 36 KB
    __shared__ float c0s[Hh];
    int b = blockIdx.y, chunk = blockIdx.x;
    int t = threadIdx.x, lane = t & 31, w = t >> 5;   // 16 warps
    for (int i = t; i < Hh*Dd; i += 512)
        ws[i] = wt[(size_t)b*Hh*Dd + i];
    if (t < Hh) c0s[t] = c0g[b*Hh + t];
    __syncthreads();

    #pragma unroll
    for (int it = 0; it < 8; it++) {
        int tok = chunk*128 + it*16 + w;
        if (tok >= Nn) break;
        const __nv_bfloat162* ar = (const __nv_bfloat162*)(ah + ((size_t)(b*Nn + tok))*Dd);
        const __nv_bfloat162* lr = (const __nv_bfloat162*)(al + ((size_t)(b*Nn + tok))*Dd);
        float af[24];
        #pragma unroll
        for (int j = 0; j < 12; j++) {
            int k2 = lane + 32*j;
            __nv_bfloat162 a2 = ar[k2], l2 = lr[k2];
            af[2*j]   = __low2float(a2)  + __low2float(l2);
            af[2*j+1] = __high2float(a2) + __high2float(l2);
        }
        #pragma unroll
        for (int h = 0; h < Hh; h++) {
            const float* wsr = ws + h*Dd;
            float s = 0.f;
            #pragma unroll
            for (int j = 0; j < 12; j++) {
                int k2 = lane + 32*j;
                s += af[2*j]*wsr[2*k2] + af[2*j+1]*wsr[2*k2+1];
            }
            #pragma unroll
            for (int off = 16; off; off >>= 1) s += __shfl_xor_sync(0xffffffff, s, off);
            if (lane == 0)
                row0g[(size_t)(b*Hh + h)*VSTR + tok] = (s + c0s[h]) * 0.125f;
        }
    }
}

// ---------------- flash attention (double-buffered K/V, no-max softmax) ------
#define KV_H 16384   // halves per K+V stage (K 8192 + V 8192)

__global__ __launch_bounds__(256) void fattn_kernel(
    const __nv_bfloat16* __restrict__ qkvh, __nv_bfloat16* __restrict__ ob)
{
    extern __shared__ __nv_bfloat16 sm[];
    __nv_bfloat16* Qh  = sm;                  // 64*64
    __nv_bfloat16* KV0 = Qh + 4096;           // stage 0: K 128*64 | V 128*64
    __nv_bfloat16* KV1 = KV0 + KV_H;          // stage 1
    __nv_bfloat16* Pm  = KV1 + KV_H;          // 64*PSTR
    float* part = (float*)(Pm + 64*PSTR);     // [2][64] warp-partial row sums
    float* lsum = part + 128;                 // [64] accumulated denominators

    int bh = blockIdx.y;
    int b = bh / Hh, h = bh - b*Hh;
    int q0 = blockIdx.x * 64;
    int t = threadIdx.x, lane = t & 31, warp = t >> 5;
    int wm = warp >> 1, wn = warp & 1;
    int g = lane >> 2, tq = lane & 3;

    const __nv_bfloat16* qsrc = qkvh + (size_t)b*Nn*(3*Dd) + h*DH;
    const __nv_bfloat16* ksrc = qsrc + Dd;
    const __nv_bfloat16* vsrc = qsrc + 2*Dd;

    auto ldt = [&](__nv_bfloat16* dst, const __nv_bfloat16* src,
                   int r0_, int rtot, int ld, int nrows) {
        int iters = nrows >> 5;
        for (int i = 0; i < iters; i++) {
            int chunk = t + i*256;
            int row = chunk >> 3;
            int kc  = chunk & 7;
            uint32_t sa = (uint32_t)__cvta_generic_to_shared(
                dst + row*64 + ((kc*8) ^ ((row&7)*8)));
            const __nv_bfloat16* gp = src + (size_t)(r0_+row)*ld + kc*8;
            int sz = (r0_+row < rtot) ? 16 : 0;
            asm volatile("cp.async.cg.shared.global [%0], [%1], 16, %2;\n"
                         :: "r"(sa), "l"(gp), "r"(sz));
        }
    };
    auto load_kv = [&](int buf, int k0) {
        __nv_bfloat16* st = (buf == 0) ? KV0 : KV1;
        ldt(st,        ksrc, k0, Nn, 3*Dd, 128);
        ldt(st + 8192, vsrc, k0, Nn, 3*Dd, 128);
        asm volatile("cp.async.commit_group;\n");
    };

    ldt(Qh, qsrc, q0, Nn, 3*Dd, 64);
    asm volatile("cp.async.commit_group;\n");
    load_kv(0, 0);                           // preload chunk 0

    if (t < 64) lsum[t] = 0.f;
    float acc_o[4][4] = {};

    int arowS = wm*16 + (lane & 15);
    int aswS  = (arowS & 7) * 16;
    int ahi   = ((lane >> 4) & 1) * 16;
    int bhi   = ((lane >> 3) & 1) * 16;
    int vrow_l = lane & 15;
    int vcol_l = ((lane >> 4) & 1) * 8;

    uint32_t baseQh = (uint32_t)__cvta_generic_to_shared(Qh);
    uint32_t basePm = (uint32_t)__cvta_generic_to_shared(Pm);

    const int NCHUNK = (Nn + 127) / 128;
    for (int c = 0; c < NCHUNK; c++) {
        int k0 = c*128;
        int limit = Nn - k0; if (limit > 128) limit = 128;
        int buf = c & 1;

        // prefetch next chunk into the other buffer (free since end-of-body sync)
        if (c + 1 < NCHUNK) {
            load_kv(buf ^ 1, k0 + 128);
            asm volatile("cp.async.wait_group 1;\n");
        } else {
            asm volatile("cp.async.wait_group 0;\n");
        }
        __syncthreads();

        uint32_t baseKh = (uint32_t)__cvta_generic_to_shared((buf == 0) ? KV0 : KV1);
        uint32_t baseVh = baseKh + 8192*2;

        // ---- S = Qh @ Kh^T ----
        float accs[8][4] = {};
        #pragma unroll
        for (int ks = 0; ks < 4; ks++) {
            uint32_t a4[4];
            int offA = arowS*128 + ((ks*32 + ahi) ^ aswS);
            ldsm4(a4[0], a4[1], a4[2], a4[3], baseQh + offA);
            uint32_t bh4[4][4];
            #pragma unroll
            for (int np = 0; np < 4; np++) {
                int brow = wn*64 + np*16 + ((lane >> 4) << 3) + (lane & 7);
                int offB = brow*128 + ((ks*32 + bhi) ^ ((brow&7)*16));
                ldsm4(bh4[np][0], bh4[np][1], bh4[np][2], bh4[np][3], baseKh + offB);
            }
            #pragma unroll
            for (int nf = 0; nf < 8; nf++)
                mma16816(accs[nf], a4, &bh4[nf>>1][(nf&1)*2]);
        }

        // ---- exp in registers -> P bf16 + per-row sums ----
        {
            int r0 = wm*16 + g, r1 = r0 + 8;
            float sum0 = 0.f, sum1 = 0.f;
            #pragma unroll
            for (int nf = 0; nf < 8; nf++) {
                int cc = wn*64 + nf*8 + tq*2;
                bool m0 = cc < limit, m1 = cc + 1 < limit;
                float e0 = m0 ? __expf(accs[nf][0]*0.125f) : 0.f;
                float e1 = m1 ? __expf(accs[nf][1]*0.125f) : 0.f;
                float e2 = m0 ? __expf(accs[nf][2]*0.125f) : 0.f;
                float e3 = m1 ? __expf(accs[nf][3]*0.125f) : 0.f;
                *(__nv_bfloat162*)(Pm + r0*PSTR + cc) = __floats2bfloat162_rn(e0, e1);
                *(__nv_bfloat162*)(Pm + r1*PSTR + cc) = __floats2bfloat162_rn(e2, e3);
                sum0 += e0 + e1;
                sum1 += e2 + e3;
            }
            sum0 += __shfl_xor_sync(0xffffffff, sum0, 1);
            sum0 += __shfl_xor_sync(0xffffffff, sum0, 2);
            sum1 += __shfl_xor_sync(0xffffffff, sum1, 1);
            sum1 += __shfl_xor_sync(0xffffffff, sum1, 2);
            if (tq == 0) { part[wn*64 + r0] = sum0; part[wn*64 + r1] = sum1; }
        }
        __syncthreads();
        if (t < 64) lsum[t] += part[t] + part[64 + t];

        // ---- O += P @ V (B fragments via trans ldmatrix on [tok][d]) ----
        {
            #pragma unroll
            for (int s = 0; s < 8; s++) {
                uint32_t a4[4];
                uint32_t offP = (uint32_t)((wm*16 + (lane & 15))*PSTR*2 + s*32 + ((lane>>4)&1)*16);
                ldsm4(a4[0], a4[1], a4[2], a4[3], basePm + offP);
                uint32_t bv[2][4];
                #pragma unroll
                for (int np = 0; np < 2; np++) {
                    int row = s*16 + vrow_l;
                    int col = wn*32 + np*16 + vcol_l;
                    int off = row*128 + ((col*2) ^ ((row&7)*16));
                    ldsm4t(bv[np][0], bv[np][1], bv[np][2], bv[np][3], baseVh + off);
                }
                #pragma unroll
                for (int nf = 0; nf < 4; nf++)
                    mma16816(acc_o[nf], a4, &bv[nf>>1][(nf&1)*2]);
            }
        }
        __syncthreads();   // end-of-body: frees this buf + Pm for next iteration
    }

    {
        int or0 = wm*16 + g, or1 = or0 + 8;
        float li0 = 1.f / lsum[or0];
        float li1 = 1.f / lsum[or1];
        int tok0 = q0 + or0, tok1 = q0 + or1;
        #pragma unroll
        for (int nf = 0; nf < 4; nf++) {
            int d = wn*32 + nf*8 + tq*2;
            if (tok0 < Nn)
                *(__nv_bfloat162*)(ob + ((size_t)(b*Nn + tok0))*Dd + h*DH + d) =
                    __floats2bfloat162_rn(acc_o[nf][0]*li0, acc_o[nf][1]*li0);
            if (tok1 < Nn)
                *(__nv_bfloat162*)(ob + ((size_t)(b*Nn + tok1))*Dd + h*DH + d) =
                    __floats2bfloat162_rn(acc_o[nf][2]*li1, acc_o[nf][3]*li1);
        }
    }
}

// ---------------- threefry2x32 for jax.random.key(42) ------------------------
__device__ __forceinline__ void tf_round(unsigned& x0, unsigned& x1, int r) {
    x0 += x1;
    x1 = ((x1 << r) | (x1 >> (32 - r))) ^ x0;
}
__device__ __forceinline__ uint2 threefry_42(unsigned c0, unsigned c1) {
    const unsigned k0 = 0u, k1 = 42u, k2 = 0x1BD11BDAu ^ 42u;
    unsigned x0 = c0 + k0, x1 = c1 + k1;
    tf_round(x0,x1,13); tf_round(x0,x1,15); tf_round(x0,x1,26); tf_round(x0,x1,6);
    x0 += k1; x1 += k2 + 1u;
    tf_round(x0,x1,17); tf_round(x0,x1,29); tf_round(x0,x1,16); tf_round(x0,x1,24);
    x0 += k2; x1 += k0 + 2u;
    tf_round(x0,x1,13); tf_round(x0,x1,15); tf_round(x0,x1,26); tf_round(x0,x1,6);
    x0 += k0; x1 += k1 + 3u;
    tf_round(x0,x1,17); tf_round(x0,x1,29); tf_round(x0,x1,16); tf_round(x0,x1,24);
    x0 += k1; x1 += k2 + 4u;
    tf_round(x0,x1,13); tf_round(x0,x1,15); tf_round(x0,x1,26); tf_round(x0,x1,6);
    x0 += k2; x1 += k0 + 5u;
    return make_uint2(x0, x1);
}

// ---------------- fused scoring: cls softmax-mean -> gumbel MC -> top-k -------
// No max subtraction: cls scores |s| ~ few units; gumbel tt in [-42, 28] -> exp
// stays finite in fp32.
__global__ __launch_bounds__(608) void score_kernel(
    const float* __restrict__ row0g, int* __restrict__ selidx, float* __restrict__ adc)
{
    __shared__ float red[19];
    __shared__ float bcast;
    __shared__ float logit_sm[NUM_PATCHES];
    __shared__ float s_sm[NUM_PATCHES];
    __shared__ int flags[NUM_PATCHES];
    int b = blockIdx.x, t = threadIdx.x;
    int lane = t & 31, w = t >> 5;

    // phase 1: cls attention row, softmax per head (no max), mean over heads
    float acc = 0.f;
    for (int h = 0; h < Hh; h++) {
        float s = (t < Nn) ? row0g[((size_t)(b*Hh + h))*VSTR + t] : 0.f;
        float e = (t < Nn) ? expf(s) : 0.f;
        float sv = e;
        #pragma unroll
        for (int off = 16; off; off >>= 1) sv += __shfl_xor_sync(0xffffffff, sv, off);
        if (lane == 0) red[w] = sv;
        __syncthreads();
        if (t == 0) {
            float ss = 0.f;
            for (int i = 0; i < 19; i++) ss += red[i];
            bcast = ss;
        }
        __syncthreads();
        acc += e / bcast;
        __syncthreads();
    }
    if (t >= 1 && t < Nn) logit_sm[t-1] = logf(acc*(1.0f/Hh) + 1e-8f);
    __syncthreads();

    // phase 2: gumbel MC softmax (no max)
    float lg = (t < NUM_PATCHES) ? logit_sm[t] : 0.f;
    float sacc = 0.f;
    for (int s = 0; s < MC_SAMPLES; s++) {
        float e = 0.f;
        if (t < NUM_PATCHES) {
            unsigned i = (unsigned)((s*Bsz + b)*NUM_PATCHES + t);
            uint2 r = threefry_42(0u, i);
            unsigned bits = r.x ^ r.y;
            float f = __uint_as_float(0x3f800000u | (bits >> 9)) - 1.0f;
            const float mn = 1e-6f, mx = 1.0f - 1e-6f;
            float u = fmaxf(f*(mx - mn) + mn, mn);
            float g = -logf(-logf(u));
            e = expf((lg + g) * 2.0f);
        }
        float sv = e;
        #pragma unroll
        for (int off = 16; off; off >>= 1) sv += __shfl_xor_sync(0xffffffff, sv, off);
        if (lane == 0) red[w] = sv;
        __syncthreads();
        if (t == 0) {
            float ss = 0.f;
            for (int i = 0; i < 19; i++) ss += red[i];
            bcast = ss;
        }
        __syncthreads();
        sacc += e / bcast;
        __syncthreads();
    }
    if (t < NUM_PATCHES) s_sm[t] = sacc * (1.0f/MC_SAMPLES);
    __syncthreads();

    // phase 3: stable top-k(288) + outputs
    if (t < NUM_PATCHES) {
        float sp = s_sm[t];
        int rank = 0;
        for (int j = 0; j < NUM_PATCHES; j++) {
            float sj = s_sm[j];
            rank += (sj > sp) || (sj == sp && j < t);
        }
        flags[t] = (rank < N_ALPHA) ? 1 : 0;
    }
    __syncthreads();
    if (t < NUM_PATCHES && flags[t]) {
        int pos = 0;
        for (int j = 0; j < t; j++) pos += flags[j];
        selidx[b*N_ALPHA + pos] = t + 1;
        adc[(size_t)b*(N_ALPHA+1) + pos + 1] = s_sm[t];
    }
    if (t == 0) adc[(size_t)b*(N_ALPHA+1)] = 1.0f;
}

// ---------------- gather selected tokens --------------------------------------
__global__ void gather_kernel(const float* __restrict__ x2,
                              const int* __restrict__ selidx, float* __restrict__ out)
{
    int j = blockIdx.x;
    int b = blockIdx.y;
    int row = (j == 0) ? 0 : selidx[b*N_ALPHA + j - 1];
    const float4* src = (const float4*)(x2 + ((size_t)b*Nn + row)*Dd);
    float4* dst = (float4*)(out + ((size_t)b*(N_ALPHA+1) + j)*Dd);
    dst[threadIdx.x] = src[threadIdx.x];
}

// ---------------- launch -------------------------------------------------------
extern "C" void kernel_launch(void* const* d_in, const int* in_sizes, int n_in,
                              void* d_out, int out_size)
{
    const float* x      = (const float*)d_in[0];
    const float* g1     = (const float*)d_in[1];
    const float* b1     = (const float*)d_in[2];
    const float* w_qkv  = (const float*)d_in[3];
    const float* b_qkv  = (const float*)d_in[4];
    const float* w_proj = (const float*)d_in[5];
    const float* b_proj = (const float*)d_in[6];
    const float* ls1    = (const float*)d_in[7];
    const float* g2     = (const float*)d_in[8];
    const float* b2     = (const float*)d_in[9];
    const float* w_fc1  = (const float*)d_in[10];
    const float* b_fc1  = (const float*)d_in[11];
    const float* w_fc2  = (const float*)d_in[12];
    const float* b_fc2  = (const float*)d_in[13];
    const float* ls2    = (const float*)d_in[14];
    float* out = (float*)d_out;

    float *x1, *x2, *row0, *q0ex, *wt, *c0;
    __nv_bfloat16 *ah, *al, *qkvh, *ob, *hb, *ffb;
    __nv_bfloat16 *wqkvT, *wprojT, *wfc1T, *wfc2T;
    int* selidx;
    cudaGetSymbolAddress((void**)&x1,     g_x1);
    cudaGetSymbolAddress((void**)&x2,     g_x2);
    cudaGetSymbolAddress((void**)&ah,     g_ah);
    cudaGetSymbolAddress((void**)&al,     g_al);
    cudaGetSymbolAddress((void**)&qkvh,   g_qkvh);
    cudaGetSymbolAddress((void**)&row0,   g_row0);
    cudaGetSymbolAddress((void**)&q0ex,   g_q0ex);
    cudaGetSymbolAddress((void**)&wt,     g_wt);
    cudaGetSymbolAddress((void**)&c0,     g_c0);
    cudaGetSymbolAddress((void**)&ob,     g_ob);
    cudaGetSymbolAddress((void**)&hb,     g_hb);
    cudaGetSymbolAddress((void**)&ffb,    g_ffb);
    cudaGetSymbolAddress((void**)&wqkvT,  g_wqkvT);
    cudaGetSymbolAddress((void**)&wprojT, g_wprojT);
    cudaGetSymbolAddress((void**)&wfc1T,  g_wfc1T);
    cudaGetSymbolAddress((void**)&wfc2T,  g_wfc2T);
    cudaGetSymbolAddress((void**)&selidx, g_selidx);

    int mblk = (Mrows + 7) / 8;
    int mtiles = (Mrows + 127) / 128;           // 289

    const int SMEM_NS = 3*2*TILE_H*2;           // 96KB (3 stages)
    cudaFuncSetAttribute(gemm_tc<4>, cudaFuncAttributeMaxDynamicSharedMemorySize, SMEM_NS);
    cudaFuncSetAttribute(gemm_tc<1>, cudaFuncAttributeMaxDynamicSharedMemorySize, SMEM_NS);
    cudaFuncSetAttribute(gemm_tc<2>, cudaFuncAttributeMaxDynamicSharedMemorySize, SMEM_NS);

    const int ATTN_SMEM = (4096 + 2*KV_H + 64*PSTR)*2 + (128+64)*4;
    cudaFuncSetAttribute(fattn_kernel, cudaFuncAttributeMaxDynamicSharedMemorySize, ATTN_SMEM);

    // 0. weight transposes
    transpose_bf16_kernel<<<dim3(3*Dd/32, Dd/32), dim3(32,8)>>>(w_qkv, wqkvT, Dd, 3*Dd);
    transpose_bf16_kernel<<<dim3(Dd/32,  Dd/32),  dim3(32,8)>>>(w_proj, wprojT, Dd,  Dd);
    transpose_bf16_kernel<<<dim3(DFF/32, Dd/32),  dim3(32,8)>>>(w_fc1,  wfc1T,  Dd,  DFF);
    transpose_bf16_kernel<<<dim3(Dd/32,  DFF/32), dim3(32,8)>>>(w_fc2,  wfc2T,  DFF, Dd);
    // 0b. exact q0 + w~ (selection-critical path, fp32 end-to-end)
    q0exact_kernel<<<Bsz, 768>>>(x, g1, b1, w_qkv, b_qkv, q0ex);
    wtilde_kernel<<<Bsz*Hh, 256>>>(w_qkv, b_qkv, q0ex, wt, c0);

    // 1. LN1 (split hi/lo bf16)
    ln_split_kernel<<<mblk, 256>>>(x, g1, b1, ah, al);
    // 2. QKV GEMM (N = 2304)
    gemm_tc<4><<<dim3(3*Dd/128, mtiles), 256, SMEM_NS>>>(
        ah, wqkvT, b_qkv, nullptr, nullptr, nullptr, qkvh, Mrows, 3*Dd, Dd, 3*Dd);
    // 3. cls-row scores (all heads per block; one pass over ah/al)
    row0_kernel<<<dim3((Nn+127)/128, Bsz), 512>>>(ah, al, wt, c0, row0);
    // 4. flash attention (double-buffered K/V)
    fattn_kernel<<<dim3((Nn+63)/64, Bsz*Hh), 256, ATTN_SMEM>>>(qkvh, ob);
    // 5. proj + residual
    gemm_tc<1><<<dim3(Dd/128, mtiles), 256, SMEM_NS>>>(
        ob, wprojT, b_proj, x, ls1, x1, nullptr, Mrows, Dd, Dd, Dd);
    // 6. LN2 (bf16 out)
    ln_kernel_bf16<<<mblk, 256>>>(x1, g2, b2, hb);
    // 7. fc1 + gelu (tanh.approx)
    gemm_tc<2><<<dim3(DFF/128, mtiles), 256, SMEM_NS>>>(
        hb, wfc1T, b_fc1, nullptr, nullptr, nullptr, ffb, Mrows, DFF, Dd, DFF);
    // 8. fc2 + residual
    gemm_tc<1><<<dim3(Dd/128, mtiles), 256, SMEM_NS>>>(
        ffb, wfc2T, b_fc2, x1, ls2, x2, nullptr, Mrows, Dd, DFF, Dd);
    // 9. fused cls -> gumbel -> top-k (adc = second output region)
    float* adc = out + (size_t)Bsz*(N_ALPHA+1)*Dd;
    score_kernel<<<Bsz, 608>>>(row0, selidx, adc);
    // 10. gather tokens
    gather_kernel<<<dim3(N_ALPHA+1, Bsz), 192>>>(x2, selidx, out);
}